// round 1
// baseline (speedup 1.0000x reference)
#include <cuda_runtime.h>

#define NN 50000
#define EDGES 1000000
#define DD 128
#define TOTE (EDGES + NN)

// ---------------- scratch (device globals; no allocation allowed) ----------------
__device__ float g_h[NN * DD];     // current conv's transformed features
__device__ float g_x1[NN * DD];    // layer-1 output (relu'd)
__device__ float g_x2o[NN * DD];   // branch-o embedding
__device__ float g_x2s[NN * DD];   // branch-s embedding
__device__ float g_ssrc[NN];
__device__ float g_sdst[NN];
__device__ int   g_deg[NN];
__device__ int   g_fill[NN];
__device__ int   g_rowptr_o[NN + 1];
__device__ int   g_rowptr_s[NN + 1];
__device__ int   g_col_o[TOTE];
__device__ int   g_col_s[TOTE];

// ---------------- CSR build ----------------
__global__ void k_deg_init() {
    int i = blockIdx.x * blockDim.x + threadIdx.x;
    if (i < NN) g_deg[i] = 1;   // self loop
}

__global__ void k_deg_count(const int* __restrict__ ei) {
    int e = blockIdx.x * blockDim.x + threadIdx.x;
    if (e < EDGES) atomicAdd(&g_deg[ei[EDGES + e]], 1);
}

// single-block chunked exclusive scan of g_deg -> rowptr
__global__ void k_scan(int graph_sel) {
    int* rowptr = graph_sel ? g_rowptr_s : g_rowptr_o;
    __shared__ int sh[1024];
    __shared__ int s_carry;
    int tid = threadIdx.x;
    if (tid == 0) s_carry = 0;
    __syncthreads();
    const int CH = 4096;
    for (int base = 0; base < NN; base += CH) {
        int idx = base + tid * 4;
        int v0 = (idx + 0 < NN) ? g_deg[idx + 0] : 0;
        int v1 = (idx + 1 < NN) ? g_deg[idx + 1] : 0;
        int v2 = (idx + 2 < NN) ? g_deg[idx + 2] : 0;
        int v3 = (idx + 3 < NN) ? g_deg[idx + 3] : 0;
        int s = v0 + v1 + v2 + v3;
        sh[tid] = s;
        __syncthreads();
        for (int off = 1; off < 1024; off <<= 1) {
            int t = (tid >= off) ? sh[tid - off] : 0;
            __syncthreads();
            sh[tid] += t;
            __syncthreads();
        }
        int incl = sh[tid];
        int total = sh[1023];
        int carry = s_carry;
        int run = carry + incl - s;
        if (idx + 0 < NN) rowptr[idx + 0] = run; run += v0;
        if (idx + 1 < NN) rowptr[idx + 1] = run; run += v1;
        if (idx + 2 < NN) rowptr[idx + 2] = run; run += v2;
        if (idx + 3 < NN) rowptr[idx + 3] = run;
        __syncthreads();
        if (tid == 0) s_carry = carry + total;
        __syncthreads();
    }
    if (tid == 0) rowptr[NN] = s_carry;
}

__global__ void k_fill_self(int graph_sel) {
    const int* rowptr = graph_sel ? g_rowptr_s : g_rowptr_o;
    int* col = graph_sel ? g_col_s : g_col_o;
    int i = blockIdx.x * blockDim.x + threadIdx.x;
    if (i < NN) {
        int p = rowptr[i];
        col[p] = i;
        g_fill[i] = p + 1;
    }
}

__global__ void k_fill_edges(const int* __restrict__ ei, int graph_sel) {
    int* col = graph_sel ? g_col_s : g_col_o;
    int e = blockIdx.x * blockDim.x + threadIdx.x;
    if (e < EDGES) {
        int s = ei[e];
        int d = ei[EDGES + e];
        int pos = atomicAdd(&g_fill[d], 1);
        col[pos] = s;
    }
}

// ---------------- GEMM: g_h = A(Mx128) @ W(128x128) ----------------
#define BM 64
#define BK 32
__global__ void k_gemm(const float* __restrict__ Xext, int use_x1,
                       const float* __restrict__ W, int M) {
    const float* A = use_x1 ? g_x1 : Xext;
    __shared__ float As[BM][BK];
    __shared__ float Bs[BK][DD];
    int tid = threadIdx.x;           // 256
    int row0 = blockIdx.x * BM;
    int tx = tid & 31;               // cols tx*4 .. +3
    int ty = tid >> 5;               // rows ty*8 .. +7
    float acc[8][4];
#pragma unroll
    for (int i = 0; i < 8; ++i)
#pragma unroll
        for (int j = 0; j < 4; ++j) acc[i][j] = 0.f;

    for (int kb = 0; kb < DD; kb += BK) {
        // A tile: 64x32 = 512 float4
#pragma unroll
        for (int i = tid; i < BM * BK / 4; i += 256) {
            int r = i >> 3;
            int c4 = i & 7;
            float4 v = make_float4(0.f, 0.f, 0.f, 0.f);
            if (row0 + r < M)
                v = *(const float4*)&A[(row0 + r) * DD + kb + c4 * 4];
            *(float4*)&As[r][c4 * 4] = v;
        }
        // B tile: 32x128 = 1024 float4
#pragma unroll
        for (int i = tid; i < BK * DD / 4; i += 256) {
            int r = i >> 5;
            int c4 = i & 31;
            *(float4*)&Bs[r][c4 * 4] = *(const float4*)&W[(kb + r) * DD + c4 * 4];
        }
        __syncthreads();
#pragma unroll
        for (int kk = 0; kk < BK; ++kk) {
            float4 b4 = *(const float4*)&Bs[kk][tx * 4];
            float br[4] = {b4.x, b4.y, b4.z, b4.w};
#pragma unroll
            for (int i = 0; i < 8; ++i) {
                float a = As[ty * 8 + i][kk];
#pragma unroll
                for (int j = 0; j < 4; ++j) acc[i][j] += a * br[j];
            }
        }
        __syncthreads();
    }
#pragma unroll
    for (int i = 0; i < 8; ++i) {
        int r = row0 + ty * 8 + i;
        if (r < M) {
            float4 v = make_float4(acc[i][0], acc[i][1], acc[i][2], acc[i][3]);
            *(float4*)&g_h[r * DD + tx * 4] = v;
        }
    }
}

// ---------------- per-node attention scalars ----------------
__global__ void k_scalars(const float* __restrict__ a_src, const float* __restrict__ a_dst) {
    int w = (blockIdx.x * blockDim.x + threadIdx.x) >> 5;
    int l = threadIdx.x & 31;
    if (w >= NN) return;
    float4 hv = ((const float4*)g_h)[w * 32 + l];
    float4 as = ((const float4*)a_src)[l];
    float4 ad = ((const float4*)a_dst)[l];
    float s1 = hv.x * as.x + hv.y * as.y + hv.z * as.z + hv.w * as.w;
    float s2 = hv.x * ad.x + hv.y * ad.y + hv.z * ad.z + hv.w * ad.w;
#pragma unroll
    for (int off = 16; off; off >>= 1) {
        s1 += __shfl_xor_sync(0xffffffffu, s1, off);
        s2 += __shfl_xor_sync(0xffffffffu, s2, off);
    }
    if (l == 0) { g_ssrc[w] = s1; g_sdst[w] = s2; }
}

// ---------------- warp-per-dst softmax + aggregate ----------------
__global__ void k_aggregate(int graph_sel, int out_sel,
                            const float* __restrict__ bias, int relu) {
    const int* rowptr = graph_sel ? g_rowptr_s : g_rowptr_o;
    const int* col    = graph_sel ? g_col_s    : g_col_o;
    float* out = (out_sel == 0) ? g_x1 : (out_sel == 1) ? g_x2o : g_x2s;
    int w = (blockIdx.x * blockDim.x + threadIdx.x) >> 5;
    int l = threadIdx.x & 31;
    if (w >= NN) return;
    int beg = rowptr[w];
    int end = rowptr[w + 1];
    float sd = g_sdst[w];
    // pass 1: segment max (strided over lanes)
    float mx = -1e30f;
    for (int e = beg + l; e < end; e += 32) {
        float z = g_ssrc[col[e]] + sd;
        z = z > 0.f ? z : 0.2f * z;
        mx = fmaxf(mx, z);
    }
#pragma unroll
    for (int off = 16; off; off >>= 1)
        mx = fmaxf(mx, __shfl_xor_sync(0xffffffffu, mx, off));
    // pass 2: weighted accumulate (all lanes walk every edge; lane owns 4 dims)
    const float4* h4 = (const float4*)g_h;
    float4 acc = make_float4(0.f, 0.f, 0.f, 0.f);
    float den = 0.f;
    for (int e = beg; e < end; ++e) {
        int s = col[e];                      // broadcast
        float z = g_ssrc[s] + sd;            // broadcast
        z = z > 0.f ? z : 0.2f * z;
        float wgt = __expf(z - mx);
        den += wgt;
        float4 hv = h4[s * 32 + l];          // 512B coalesced per warp
        acc.x += wgt * hv.x;
        acc.y += wgt * hv.y;
        acc.z += wgt * hv.z;
        acc.w += wgt * hv.w;
    }
    float inv = 1.f / (den + 1e-16f);
    float4 bv = ((const float4*)bias)[l];
    float4 o;
    o.x = acc.x * inv + bv.x;
    o.y = acc.y * inv + bv.y;
    o.z = acc.z * inv + bv.z;
    o.w = acc.w * inv + bv.w;
    if (relu) {
        o.x = fmaxf(o.x, 0.f); o.y = fmaxf(o.y, 0.f);
        o.z = fmaxf(o.z, 0.f); o.w = fmaxf(o.w, 0.f);
    }
    ((float4*)out)[w * 32 + l] = o;
}

// ---------------- prediction head ----------------
__global__ void k_pred(const float* __restrict__ degree,
                       const float* __restrict__ Wp,
                       const float* __restrict__ bp,
                       float* __restrict__ out) {
    int v = (blockIdx.x * blockDim.x + threadIdx.x) >> 5;
    int l = threadIdx.x & 31;
    if (v >= NN) return;
    float4 xo = ((const float4*)g_x2o)[v * 32 + l];
    float4 xs = ((const float4*)g_x2s)[v * 32 + l];
    float dg = degree[v * 32 + l];  // D_DEG = 32, one per lane
    int k0 = l * 4;
    float z0 = xo.x * Wp[(k0 + 0) * 2] + xo.y * Wp[(k0 + 1) * 2]
             + xo.z * Wp[(k0 + 2) * 2] + xo.w * Wp[(k0 + 3) * 2]
             + xs.x * Wp[(128 + k0 + 0) * 2] + xs.y * Wp[(128 + k0 + 1) * 2]
             + xs.z * Wp[(128 + k0 + 2) * 2] + xs.w * Wp[(128 + k0 + 3) * 2]
             + dg * Wp[(256 + l) * 2];
    float z1 = xo.x * Wp[(k0 + 0) * 2 + 1] + xo.y * Wp[(k0 + 1) * 2 + 1]
             + xo.z * Wp[(k0 + 2) * 2 + 1] + xo.w * Wp[(k0 + 3) * 2 + 1]
             + xs.x * Wp[(128 + k0 + 0) * 2 + 1] + xs.y * Wp[(128 + k0 + 1) * 2 + 1]
             + xs.z * Wp[(128 + k0 + 2) * 2 + 1] + xs.w * Wp[(128 + k0 + 3) * 2 + 1]
             + dg * Wp[(256 + l) * 2 + 1];
#pragma unroll
    for (int off = 16; off; off >>= 1) {
        z0 += __shfl_xor_sync(0xffffffffu, z0, off);
        z1 += __shfl_xor_sync(0xffffffffu, z1, off);
    }
    z0 += bp[0];
    z1 += bp[1];
    float mz = fmaxf(z0, z1);
    float e0 = __expf(z0 - mz), e1 = __expf(z1 - mz);
    float inv = 1.f / (e0 + e1);
    float a0 = e0 * inv, a1 = e1 * inv;
    float4 o;
    o.x = a0 * xo.x + a1 * xs.x;
    o.y = a0 * xo.y + a1 * xs.y;
    o.z = a0 * xo.z + a1 * xs.z;
    o.w = a0 * xo.w + a1 * xs.w;
    ((float4*)out)[v * 32 + l] = o;
}

// ---------------- host orchestration ----------------
static void build_csr(const int* ei, int gsel) {
    k_deg_init<<<(NN + 255) / 256, 256>>>();
    k_deg_count<<<(EDGES + 255) / 256, 256>>>(ei);
    k_scan<<<1, 1024>>>(gsel);
    k_fill_self<<<(NN + 255) / 256, 256>>>(gsel);
    k_fill_edges<<<(EDGES + 255) / 256, 256>>>(ei, gsel);
}

static void run_conv(const float* Xext, int use_x1,
                     const float* W, const float* asrc, const float* adst,
                     const float* bias, int gsel, int out_sel, int relu) {
    k_gemm<<<(NN + BM - 1) / BM, 256>>>(Xext, use_x1, W, NN);
    k_scalars<<<NN / 8, 256>>>(asrc, adst);
    k_aggregate<<<NN / 8, 256>>>(gsel, out_sel, bias, relu);
}

extern "C" void kernel_launch(void* const* d_in, const int* in_sizes, int n_in,
                              void* d_out, int out_size) {
    const float* x_o    = (const float*)d_in[0];
    const float* degree = (const float*)d_in[1];
    const int *ei_o, *ei_s;
    int base;
    if (in_sizes[2] == 2 * EDGES) {          // setup_inputs dict order
        ei_o = (const int*)d_in[2];
        ei_s = (const int*)d_in[3];
        base = 4;
    } else {                                  // reference signature order
        base = 2;
        ei_o = (const int*)d_in[20];
        ei_s = (const int*)d_in[21];
    }
    const float* W_o1 = (const float*)d_in[base + 0];
    const float* a_src_o1 = (const float*)d_in[base + 1];
    const float* a_dst_o1 = (const float*)d_in[base + 2];
    const float* b_o1 = (const float*)d_in[base + 3];
    const float* W_o2 = (const float*)d_in[base + 4];
    const float* a_src_o2 = (const float*)d_in[base + 5];
    const float* a_dst_o2 = (const float*)d_in[base + 6];
    const float* b_o2 = (const float*)d_in[base + 7];
    const float* W_s1 = (const float*)d_in[base + 8];
    const float* a_src_s1 = (const float*)d_in[base + 9];
    const float* a_dst_s1 = (const float*)d_in[base + 10];
    const float* b_s1 = (const float*)d_in[base + 11];
    const float* W_s2 = (const float*)d_in[base + 12];
    const float* a_src_s2 = (const float*)d_in[base + 13];
    const float* a_dst_s2 = (const float*)d_in[base + 14];
    const float* b_s2 = (const float*)d_in[base + 15];
    const float* W_pred = (const float*)d_in[base + 16];
    const float* b_pred = (const float*)d_in[base + 17];
    float* out = (float*)d_out;

    // branch o
    build_csr(ei_o, 0);
    run_conv(x_o, 0, W_o1, a_src_o1, a_dst_o1, b_o1, 0, /*out=x1*/0, /*relu*/1);
    run_conv(nullptr, 1, W_o2, a_src_o2, a_dst_o2, b_o2, 0, /*out=x2o*/1, 0);
    // branch s
    build_csr(ei_s, 1);
    run_conv(x_o, 0, W_s1, a_src_s1, a_dst_s1, b_s1, 1, /*out=x1*/0, 1);
    run_conv(nullptr, 1, W_s2, a_src_s2, a_dst_s2, b_s2, 1, /*out=x2s*/2, 0);
    // head
    k_pred<<<NN / 8, 256>>>(degree, W_pred, b_pred, out);
}

// round 2
// speedup vs baseline: 1.1001x; 1.1001x over previous
#include <cuda_runtime.h>

#define NN 50000
#define EDGES 1000000
#define DD 128
#define TOTE (EDGES + NN)

// ---------------- scratch ----------------
__device__ float g_h[NN * DD];
__device__ float g_x1[NN * DD];
__device__ float g_x2o[NN * DD];
__device__ float g_x2s[NN * DD];
__device__ float g_ssrc[NN];
__device__ float g_sdst[NN];
__device__ unsigned g_gmax[8];          // 2 slots per conv (enc'd float max)
__device__ int   g_deg[NN];
__device__ int   g_fill[NN];
__device__ int   g_bsum[64];
__device__ int   g_boff[64];
__device__ int   g_rowptr_o[NN + 1];
__device__ int   g_rowptr_s[NN + 1];
__device__ int   g_col_o[TOTE];
__device__ int   g_col_s[TOTE];

__device__ __forceinline__ unsigned encf(float f) {
    unsigned u = __float_as_uint(f);
    return (u & 0x80000000u) ? ~u : (u | 0x80000000u);
}
__device__ __forceinline__ float decf(unsigned u) {
    return __uint_as_float((u & 0x80000000u) ? (u & 0x7fffffffu) : ~u);
}
__device__ __forceinline__ float lrelu(float z) { return z > 0.f ? z : 0.2f * z; }

// ---------------- CSR build ----------------
__global__ void k_deg_init() {
    int i = blockIdx.x * blockDim.x + threadIdx.x;
    if (i < NN) g_deg[i] = 1;               // self loop
    if (i < 8) g_gmax[i] = encf(-1e30f);
}

__global__ void k_deg_count(const int* __restrict__ ei) {
    int e = blockIdx.x * blockDim.x + threadIdx.x;
    if (e < EDGES) atomicAdd(&g_deg[ei[EDGES + e]], 1);
}

// local inclusive scan per 1024-block; writes local-exclusive into rowptr, block sum
__global__ void k_scan_local(int gsel) {
    int* rowptr = gsel ? g_rowptr_s : g_rowptr_o;
    __shared__ int sh[1024];
    int tid = threadIdx.x;
    int idx = blockIdx.x * 1024 + tid;
    int v = (idx < NN) ? g_deg[idx] : 0;
    sh[tid] = v;
    __syncthreads();
    for (int off = 1; off < 1024; off <<= 1) {
        int t = (tid >= off) ? sh[tid - off] : 0;
        __syncthreads();
        sh[tid] += t;
        __syncthreads();
    }
    if (idx < NN) rowptr[idx] = sh[tid] - v;      // local exclusive
    if (tid == 1023) g_bsum[blockIdx.x] = sh[tid];
}

__global__ void k_scan_block() {
    __shared__ int sh[64];
    int tid = threadIdx.x;   // 64 threads
    int v = (tid < 49) ? g_bsum[tid] : 0;
    sh[tid] = v;
    __syncthreads();
    for (int off = 1; off < 64; off <<= 1) {
        int t = (tid >= off) ? sh[tid - off] : 0;
        __syncthreads();
        sh[tid] += t;
        __syncthreads();
    }
    g_boff[tid] = sh[tid] - v;
}

__global__ void k_fill_self(int gsel) {
    int* rowptr = gsel ? g_rowptr_s : g_rowptr_o;
    int* col = gsel ? g_col_s : g_col_o;
    int idx = blockIdx.x * 1024 + threadIdx.x;
    if (idx < NN) {
        int p = rowptr[idx] + g_boff[idx >> 10];
        rowptr[idx] = p;
        col[p] = idx;
        g_fill[idx] = p + 1;
    }
    if (idx == 0) rowptr[NN] = TOTE;
}

__global__ void k_fill_edges(const int* __restrict__ ei, int gsel) {
    int* col = gsel ? g_col_s : g_col_o;
    int e = blockIdx.x * blockDim.x + threadIdx.x;
    if (e < EDGES) {
        int s = ei[e];
        int d = ei[EDGES + e];
        int pos = atomicAdd(&g_fill[d], 1);
        col[pos] = s;
    }
}

// ---------------- GEMM 128x128x128 + fused attention scalars ----------------
#define GBM 128
#define GBK 16
#define APAD 4
__global__ __launch_bounds__(256, 2) void k_gemm(
    const float* __restrict__ Xext, int use_x1,
    const float* __restrict__ W,
    const float* __restrict__ a_src, const float* __restrict__ a_dst,
    int slot)
{
    const float* A = use_x1 ? g_x1 : Xext;
    __shared__ float As[GBK][GBM + APAD];   // transposed: As[k][m]
    __shared__ float Bs[GBK][DD];
    int tid = threadIdx.x;
    int row0 = blockIdx.x * GBM;
    int tx = tid & 15;
    int ty = tid >> 4;
    int m0 = ty * 8;
    int na = tx * 4;          // cols na..na+3 and 64+na..64+na+3
    float acc[8][8];
#pragma unroll
    for (int i = 0; i < 8; ++i)
#pragma unroll
        for (int j = 0; j < 8; ++j) acc[i][j] = 0.f;

    for (int kb = 0; kb < DD; kb += GBK) {
        // A tile (coalesced): 512 float4, 2 per thread; transpose into As
#pragma unroll
        for (int t = 0; t < 2; ++t) {
            int i = tid + t * 256;
            int r = i >> 2;          // 0..127
            int j = i & 3;           // which float4 within the 16-k row chunk
            float4 v = make_float4(0.f, 0.f, 0.f, 0.f);
            if (row0 + r < NN) v = *(const float4*)&A[(row0 + r) * DD + kb + j * 4];
            As[j * 4 + 0][r] = v.x;
            As[j * 4 + 1][r] = v.y;
            As[j * 4 + 2][r] = v.z;
            As[j * 4 + 3][r] = v.w;
        }
        // B tile: 512 float4, 2 per thread
#pragma unroll
        for (int t = 0; t < 2; ++t) {
            int i = tid + t * 256;
            int r = i >> 5;
            int c = i & 31;
            *(float4*)&Bs[r][c * 4] = *(const float4*)&W[(kb + r) * DD + c * 4];
        }
        __syncthreads();
#pragma unroll
        for (int kk = 0; kk < GBK; ++kk) {
            float a8[8], b8[8];
            *(float4*)&a8[0] = *(const float4*)&As[kk][m0];
            *(float4*)&a8[4] = *(const float4*)&As[kk][m0 + 4];
            *(float4*)&b8[0] = *(const float4*)&Bs[kk][na];
            *(float4*)&b8[4] = *(const float4*)&Bs[kk][64 + na];
#pragma unroll
            for (int i = 0; i < 8; ++i)
#pragma unroll
                for (int j = 0; j < 8; ++j) acc[i][j] += a8[i] * b8[j];
        }
        __syncthreads();
    }

    // epilogue: write h, compute per-row s_src/s_dst partials
    float as8[8], ad8[8];
    *(float4*)&as8[0] = *(const float4*)&a_src[na];
    *(float4*)&as8[4] = *(const float4*)&a_src[64 + na];
    *(float4*)&ad8[0] = *(const float4*)&a_dst[na];
    *(float4*)&ad8[4] = *(const float4*)&a_dst[64 + na];
    float ps[8], pd[8];
#pragma unroll
    for (int i = 0; i < 8; ++i) {
        float s1 = 0.f, s2 = 0.f;
#pragma unroll
        for (int j = 0; j < 8; ++j) {
            s1 += acc[i][j] * as8[j];
            s2 += acc[i][j] * ad8[j];
        }
        ps[i] = s1; pd[i] = s2;
    }
    // reduce across the 16 tx lanes (half-warp)
#pragma unroll
    for (int off = 1; off < 16; off <<= 1) {
#pragma unroll
        for (int i = 0; i < 8; ++i) {
            ps[i] += __shfl_xor_sync(0xffffffffu, ps[i], off);
            pd[i] += __shfl_xor_sync(0xffffffffu, pd[i], off);
        }
    }
#pragma unroll
    for (int i = 0; i < 8; ++i) {
        int r = row0 + m0 + i;
        if (r < NN) {
            float4 v0 = make_float4(acc[i][0], acc[i][1], acc[i][2], acc[i][3]);
            float4 v1 = make_float4(acc[i][4], acc[i][5], acc[i][6], acc[i][7]);
            *(float4*)&g_h[r * DD + na] = v0;
            *(float4*)&g_h[r * DD + 64 + na] = v1;
            if (tx == 0) {
                g_ssrc[r] = ps[i];
                g_sdst[r] = pd[i];
                atomicMax(&g_gmax[2 * slot], encf(ps[i]));
                atomicMax(&g_gmax[2 * slot + 1], encf(pd[i]));
            }
        }
    }
}

// ---------------- single-pass softmax aggregate (warp per dst) ----------------
__global__ __launch_bounds__(256) void k_aggregate(int gsel, int out_sel,
                                                   const float* __restrict__ bias,
                                                   int relu, int slot) {
    const int* __restrict__ rowptr = gsel ? g_rowptr_s : g_rowptr_o;
    const int* __restrict__ col    = gsel ? g_col_s    : g_col_o;
    float* out = (out_sel == 0) ? g_x1 : (out_sel == 1) ? g_x2o : g_x2s;
    int w = (blockIdx.x * blockDim.x + threadIdx.x) >> 5;
    int l = threadIdx.x & 31;
    if (w >= NN) return;
    float c = lrelu(decf(g_gmax[2 * slot]) + decf(g_gmax[2 * slot + 1]));
    int beg = rowptr[w];
    int end = rowptr[w + 1];
    float sd = g_sdst[w] - 0.f;
    const float4* __restrict__ h4 = (const float4*)g_h;
    const float* __restrict__ ss = g_ssrc;
    float4 acc = make_float4(0.f, 0.f, 0.f, 0.f);
    float den = 0.f;
    int e = beg;
    for (; e + 4 <= end; e += 4) {
        int s0 = col[e], s1 = col[e + 1], s2 = col[e + 2], s3 = col[e + 3];
        float z0 = ss[s0] + sd, z1 = ss[s1] + sd, z2 = ss[s2] + sd, z3 = ss[s3] + sd;
        float w0 = __expf(lrelu(z0) - c);
        float w1 = __expf(lrelu(z1) - c);
        float w2 = __expf(lrelu(z2) - c);
        float w3 = __expf(lrelu(z3) - c);
        float4 h0 = h4[s0 * 32 + l];
        float4 h1 = h4[s1 * 32 + l];
        float4 h2 = h4[s2 * 32 + l];
        float4 h3 = h4[s3 * 32 + l];
        den += (w0 + w1) + (w2 + w3);
        acc.x += w0 * h0.x + w1 * h1.x + w2 * h2.x + w3 * h3.x;
        acc.y += w0 * h0.y + w1 * h1.y + w2 * h2.y + w3 * h3.y;
        acc.z += w0 * h0.z + w1 * h1.z + w2 * h2.z + w3 * h3.z;
        acc.w += w0 * h0.w + w1 * h1.w + w2 * h2.w + w3 * h3.w;
    }
    for (; e < end; ++e) {
        int s = col[e];
        float wgt = __expf(lrelu(ss[s] + sd) - c);
        float4 hv = h4[s * 32 + l];
        den += wgt;
        acc.x += wgt * hv.x; acc.y += wgt * hv.y;
        acc.z += wgt * hv.z; acc.w += wgt * hv.w;
    }
    float inv = 1.f / (den + 1e-16f);
    float4 bv = ((const float4*)bias)[l];
    float4 o;
    o.x = acc.x * inv + bv.x;
    o.y = acc.y * inv + bv.y;
    o.z = acc.z * inv + bv.z;
    o.w = acc.w * inv + bv.w;
    if (relu) {
        o.x = fmaxf(o.x, 0.f); o.y = fmaxf(o.y, 0.f);
        o.z = fmaxf(o.z, 0.f); o.w = fmaxf(o.w, 0.f);
    }
    ((float4*)out)[w * 32 + l] = o;
}

// ---------------- prediction head ----------------
__global__ void k_pred(const float* __restrict__ degree,
                       const float* __restrict__ Wp,
                       const float* __restrict__ bp,
                       float* __restrict__ out) {
    int v = (blockIdx.x * blockDim.x + threadIdx.x) >> 5;
    int l = threadIdx.x & 31;
    if (v >= NN) return;
    float4 xo = ((const float4*)g_x2o)[v * 32 + l];
    float4 xs = ((const float4*)g_x2s)[v * 32 + l];
    float dg = degree[v * 32 + l];
    int k0 = l * 4;
    float z0 = xo.x * Wp[(k0 + 0) * 2] + xo.y * Wp[(k0 + 1) * 2]
             + xo.z * Wp[(k0 + 2) * 2] + xo.w * Wp[(k0 + 3) * 2]
             + xs.x * Wp[(128 + k0 + 0) * 2] + xs.y * Wp[(128 + k0 + 1) * 2]
             + xs.z * Wp[(128 + k0 + 2) * 2] + xs.w * Wp[(128 + k0 + 3) * 2]
             + dg * Wp[(256 + l) * 2];
    float z1 = xo.x * Wp[(k0 + 0) * 2 + 1] + xo.y * Wp[(k0 + 1) * 2 + 1]
             + xo.z * Wp[(k0 + 2) * 2 + 1] + xo.w * Wp[(k0 + 3) * 2 + 1]
             + xs.x * Wp[(128 + k0 + 0) * 2 + 1] + xs.y * Wp[(128 + k0 + 1) * 2 + 1]
             + xs.z * Wp[(128 + k0 + 2) * 2 + 1] + xs.w * Wp[(128 + k0 + 3) * 2 + 1]
             + dg * Wp[(256 + l) * 2 + 1];
#pragma unroll
    for (int off = 16; off; off >>= 1) {
        z0 += __shfl_xor_sync(0xffffffffu, z0, off);
        z1 += __shfl_xor_sync(0xffffffffu, z1, off);
    }
    z0 += bp[0];
    z1 += bp[1];
    float mz = fmaxf(z0, z1);
    float e0 = __expf(z0 - mz), e1 = __expf(z1 - mz);
    float inv = 1.f / (e0 + e1);
    float a0 = e0 * inv, a1 = e1 * inv;
    float4 o;
    o.x = a0 * xo.x + a1 * xs.x;
    o.y = a0 * xo.y + a1 * xs.y;
    o.z = a0 * xo.z + a1 * xs.z;
    o.w = a0 * xo.w + a1 * xs.w;
    ((float4*)out)[v * 32 + l] = o;
}

// ---------------- host orchestration ----------------
static void build_csr(const int* ei, int gsel) {
    k_deg_init<<<(NN + 255) / 256, 256>>>();
    k_deg_count<<<(EDGES + 255) / 256, 256>>>(ei);
    k_scan_local<<<49, 1024>>>(gsel);
    k_scan_block<<<1, 64>>>();
    k_fill_self<<<49, 1024>>>(gsel);
    k_fill_edges<<<(EDGES + 255) / 256, 256>>>(ei, gsel);
}

static void run_conv(const float* Xext, int use_x1,
                     const float* W, const float* asrc, const float* adst,
                     const float* bias, int gsel, int out_sel, int relu, int slot) {
    k_gemm<<<(NN + GBM - 1) / GBM, 256>>>(Xext, use_x1, W, asrc, adst, slot);
    k_aggregate<<<NN / 8, 256>>>(gsel, out_sel, bias, relu, slot);
}

extern "C" void kernel_launch(void* const* d_in, const int* in_sizes, int n_in,
                              void* d_out, int out_size) {
    const float* x_o    = (const float*)d_in[0];
    const float* degree = (const float*)d_in[1];
    const int *ei_o, *ei_s;
    int base;
    if (in_sizes[2] == 2 * EDGES) {
        ei_o = (const int*)d_in[2];
        ei_s = (const int*)d_in[3];
        base = 4;
    } else {
        base = 2;
        ei_o = (const int*)d_in[20];
        ei_s = (const int*)d_in[21];
    }
    const float* W_o1 = (const float*)d_in[base + 0];
    const float* a_src_o1 = (const float*)d_in[base + 1];
    const float* a_dst_o1 = (const float*)d_in[base + 2];
    const float* b_o1 = (const float*)d_in[base + 3];
    const float* W_o2 = (const float*)d_in[base + 4];
    const float* a_src_o2 = (const float*)d_in[base + 5];
    const float* a_dst_o2 = (const float*)d_in[base + 6];
    const float* b_o2 = (const float*)d_in[base + 7];
    const float* W_s1 = (const float*)d_in[base + 8];
    const float* a_src_s1 = (const float*)d_in[base + 9];
    const float* a_dst_s1 = (const float*)d_in[base + 10];
    const float* b_s1 = (const float*)d_in[base + 11];
    const float* W_s2 = (const float*)d_in[base + 12];
    const float* a_src_s2 = (const float*)d_in[base + 13];
    const float* a_dst_s2 = (const float*)d_in[base + 14];
    const float* b_s2 = (const float*)d_in[base + 15];
    const float* W_pred = (const float*)d_in[base + 16];
    const float* b_pred = (const float*)d_in[base + 17];
    float* out = (float*)d_out;

    build_csr(ei_o, 0);
    run_conv(x_o, 0, W_o1, a_src_o1, a_dst_o1, b_o1, 0, 0, 1, 0);
    run_conv(nullptr, 1, W_o2, a_src_o2, a_dst_o2, b_o2, 0, 1, 0, 1);
    build_csr(ei_s, 1);
    run_conv(x_o, 0, W_s1, a_src_s1, a_dst_s1, b_s1, 1, 0, 1, 2);
    run_conv(nullptr, 1, W_s2, a_src_s2, a_dst_s2, b_s2, 1, 2, 0, 3);
    k_pred<<<NN / 8, 256>>>(degree, W_pred, b_pred, out);
}

// round 3
// speedup vs baseline: 1.3327x; 1.2114x over previous
#include <cuda_runtime.h>
#include <cuda_fp16.h>

#define NN 50000
#define EDGES 1000000
#define DD 128
#define TOTE (EDGES + NN)

// ---------------- scratch ----------------
__device__ __half g_h16[NN * DD];   // transformed features (fp16, gather-optimized)
__device__ float g_x1[NN * DD];
__device__ float g_x2o[NN * DD];
__device__ float g_x2s[NN * DD];
__device__ float g_ssrc[NN];
__device__ float g_sdst[NN];
__device__ unsigned g_gmax[8];
__device__ int   g_deg[NN];
__device__ int   g_fill[NN];
__device__ int   g_bsum[64];
__device__ int   g_boff[64];
__device__ int   g_rowptr_o[NN + 1];
__device__ int   g_rowptr_s[NN + 1];
__device__ int   g_col_o[TOTE];
__device__ int   g_col_s[TOTE];

__device__ __forceinline__ unsigned encf(float f) {
    unsigned u = __float_as_uint(f);
    return (u & 0x80000000u) ? ~u : (u | 0x80000000u);
}
__device__ __forceinline__ float decf(unsigned u) {
    return __uint_as_float((u & 0x80000000u) ? (u & 0x7fffffffu) : ~u);
}
__device__ __forceinline__ float lrelu(float z) { return z > 0.f ? z : 0.2f * z; }

// ---------------- CSR build ----------------
__global__ void k_deg_init() {
    int i = blockIdx.x * blockDim.x + threadIdx.x;
    if (i < NN) g_deg[i] = 1;
    if (i < 8) g_gmax[i] = encf(-1e30f);
}

__global__ void k_deg_count(const int* __restrict__ ei) {
    int e = blockIdx.x * blockDim.x + threadIdx.x;
    if (e < EDGES) atomicAdd(&g_deg[ei[EDGES + e]], 1);
}

__global__ void k_scan_local(int gsel) {
    int* rowptr = gsel ? g_rowptr_s : g_rowptr_o;
    __shared__ int sh[1024];
    int tid = threadIdx.x;
    int idx = blockIdx.x * 1024 + tid;
    int v = (idx < NN) ? g_deg[idx] : 0;
    sh[tid] = v;
    __syncthreads();
    for (int off = 1; off < 1024; off <<= 1) {
        int t = (tid >= off) ? sh[tid - off] : 0;
        __syncthreads();
        sh[tid] += t;
        __syncthreads();
    }
    if (idx < NN) rowptr[idx] = sh[tid] - v;
    if (tid == 1023) g_bsum[blockIdx.x] = sh[tid];
}

__global__ void k_scan_block() {
    __shared__ int sh[64];
    int tid = threadIdx.x;
    int v = (tid < 49) ? g_bsum[tid] : 0;
    sh[tid] = v;
    __syncthreads();
    for (int off = 1; off < 64; off <<= 1) {
        int t = (tid >= off) ? sh[tid - off] : 0;
        __syncthreads();
        sh[tid] += t;
        __syncthreads();
    }
    g_boff[tid] = sh[tid] - v;
}

__global__ void k_fill_self(int gsel) {
    int* rowptr = gsel ? g_rowptr_s : g_rowptr_o;
    int* col = gsel ? g_col_s : g_col_o;
    int idx = blockIdx.x * 1024 + threadIdx.x;
    if (idx < NN) {
        int p = rowptr[idx] + g_boff[idx >> 10];
        rowptr[idx] = p;
        col[p] = idx;
        g_fill[idx] = p + 1;
    }
    if (idx == 0) rowptr[NN] = TOTE;
}

__global__ void k_fill_edges(const int* __restrict__ ei, int gsel) {
    int* col = gsel ? g_col_s : g_col_o;
    int e = blockIdx.x * blockDim.x + threadIdx.x;
    if (e < EDGES) {
        int s = ei[e];
        int d = ei[EDGES + e];
        int pos = atomicAdd(&g_fill[d], 1);
        col[pos] = s;
    }
}

// ---------------- GEMM 128x128x128 + fused scalars + fp16 store ----------------
#define GBM 128
#define GBK 16
#define APAD 4
__global__ __launch_bounds__(256, 2) void k_gemm(
    const float* __restrict__ Xext, int use_x1,
    const float* __restrict__ W,
    const float* __restrict__ a_src, const float* __restrict__ a_dst,
    int slot)
{
    const float* A = use_x1 ? g_x1 : Xext;
    __shared__ float As[GBK][GBM + APAD];
    __shared__ float Bs[GBK][DD];
    __shared__ float s_red[8][2];
    int tid = threadIdx.x;
    int row0 = blockIdx.x * GBM;
    int tx = tid & 15;
    int ty = tid >> 4;
    int m0 = ty * 8;
    int na = tx * 4;
    float acc[8][8];
#pragma unroll
    for (int i = 0; i < 8; ++i)
#pragma unroll
        for (int j = 0; j < 8; ++j) acc[i][j] = 0.f;

    for (int kb = 0; kb < DD; kb += GBK) {
#pragma unroll
        for (int t = 0; t < 2; ++t) {
            int i = tid + t * 256;
            int r = i >> 2;
            int j = i & 3;
            float4 v = make_float4(0.f, 0.f, 0.f, 0.f);
            if (row0 + r < NN) v = *(const float4*)&A[(row0 + r) * DD + kb + j * 4];
            As[j * 4 + 0][r] = v.x;
            As[j * 4 + 1][r] = v.y;
            As[j * 4 + 2][r] = v.z;
            As[j * 4 + 3][r] = v.w;
        }
#pragma unroll
        for (int t = 0; t < 2; ++t) {
            int i = tid + t * 256;
            int r = i >> 5;
            int c = i & 31;
            *(float4*)&Bs[r][c * 4] = *(const float4*)&W[(kb + r) * DD + c * 4];
        }
        __syncthreads();
#pragma unroll
        for (int kk = 0; kk < GBK; ++kk) {
            float a8[8], b8[8];
            *(float4*)&a8[0] = *(const float4*)&As[kk][m0];
            *(float4*)&a8[4] = *(const float4*)&As[kk][m0 + 4];
            *(float4*)&b8[0] = *(const float4*)&Bs[kk][na];
            *(float4*)&b8[4] = *(const float4*)&Bs[kk][64 + na];
#pragma unroll
            for (int i = 0; i < 8; ++i)
#pragma unroll
                for (int j = 0; j < 8; ++j) acc[i][j] += a8[i] * b8[j];
        }
        __syncthreads();
    }

    // epilogue: per-row s_src/s_dst partials
    float as8[8], ad8[8];
    *(float4*)&as8[0] = *(const float4*)&a_src[na];
    *(float4*)&as8[4] = *(const float4*)&a_src[64 + na];
    *(float4*)&ad8[0] = *(const float4*)&a_dst[na];
    *(float4*)&ad8[4] = *(const float4*)&a_dst[64 + na];
    float ps[8], pd[8];
#pragma unroll
    for (int i = 0; i < 8; ++i) {
        float s1 = 0.f, s2 = 0.f;
#pragma unroll
        for (int j = 0; j < 8; ++j) {
            s1 += acc[i][j] * as8[j];
            s2 += acc[i][j] * ad8[j];
        }
        ps[i] = s1; pd[i] = s2;
    }
#pragma unroll
    for (int off = 1; off < 16; off <<= 1) {
#pragma unroll
        for (int i = 0; i < 8; ++i) {
            ps[i] += __shfl_xor_sync(0xffffffffu, ps[i], off);
            pd[i] += __shfl_xor_sync(0xffffffffu, pd[i], off);
        }
    }
    // write h (fp16) + scalars
#pragma unroll
    for (int i = 0; i < 8; ++i) {
        int r = row0 + m0 + i;
        if (r < NN) {
            __half2 p0 = __floats2half2_rn(acc[i][0], acc[i][1]);
            __half2 p1 = __floats2half2_rn(acc[i][2], acc[i][3]);
            __half2 p2 = __floats2half2_rn(acc[i][4], acc[i][5]);
            __half2 p3 = __floats2half2_rn(acc[i][6], acc[i][7]);
            __half2* dst0 = (__half2*)&g_h16[r * DD + na];
            __half2* dst1 = (__half2*)&g_h16[r * DD + 64 + na];
            dst0[0] = p0; dst0[1] = p1;
            dst1[0] = p2; dst1[1] = p3;
            if (tx == 0) {
                g_ssrc[r] = ps[i];
                g_sdst[r] = pd[i];
            }
        }
    }
    // block-level max -> ONE atomic pair per block (was 50K same-addr atomics)
    float lms = -1e30f, lmd = -1e30f;
#pragma unroll
    for (int i = 0; i < 8; ++i) {
        lms = fmaxf(lms, ps[i]);
        lmd = fmaxf(lmd, pd[i]);
    }
#pragma unroll
    for (int off = 16; off; off >>= 1) {
        lms = fmaxf(lms, __shfl_xor_sync(0xffffffffu, lms, off));
        lmd = fmaxf(lmd, __shfl_xor_sync(0xffffffffu, lmd, off));
    }
    if ((tid & 31) == 0) { s_red[tid >> 5][0] = lms; s_red[tid >> 5][1] = lmd; }
    __syncthreads();
    if (tid == 0) {
        float ms = s_red[0][0], md = s_red[0][1];
#pragma unroll
        for (int i = 1; i < 8; ++i) {
            ms = fmaxf(ms, s_red[i][0]);
            md = fmaxf(md, s_red[i][1]);
        }
        atomicMax(&g_gmax[2 * slot], encf(ms));
        atomicMax(&g_gmax[2 * slot + 1], encf(md));
    }
}

// ---------------- single-pass softmax aggregate (warp per dst, fp16 gather) ----------------
__global__ __launch_bounds__(256) void k_aggregate(int gsel, int out_sel,
                                                   const float* __restrict__ bias,
                                                   int relu, int slot) {
    const int* __restrict__ rowptr = gsel ? g_rowptr_s : g_rowptr_o;
    const int* __restrict__ col    = gsel ? g_col_s    : g_col_o;
    float* out = (out_sel == 0) ? g_x1 : (out_sel == 1) ? g_x2o : g_x2s;
    int w = (blockIdx.x * blockDim.x + threadIdx.x) >> 5;
    int l = threadIdx.x & 31;
    if (w >= NN) return;
    float c = lrelu(decf(g_gmax[2 * slot]) + decf(g_gmax[2 * slot + 1]));
    int beg = rowptr[w];
    int end = rowptr[w + 1];
    float sd = g_sdst[w];
    const uint2* __restrict__ h2 = (const uint2*)g_h16;
    const float* __restrict__ ss = g_ssrc;
    float4 acc = make_float4(0.f, 0.f, 0.f, 0.f);
    float den = 0.f;
    int e = beg;
    for (; e + 4 <= end; e += 4) {
        int s0 = col[e], s1 = col[e + 1], s2 = col[e + 2], s3 = col[e + 3];
        float w0 = __expf(lrelu(ss[s0] + sd) - c);
        float w1 = __expf(lrelu(ss[s1] + sd) - c);
        float w2 = __expf(lrelu(ss[s2] + sd) - c);
        float w3 = __expf(lrelu(ss[s3] + sd) - c);
        uint2 r0 = h2[s0 * 32 + l];
        uint2 r1 = h2[s1 * 32 + l];
        uint2 r2 = h2[s2 * 32 + l];
        uint2 r3 = h2[s3 * 32 + l];
        den += (w0 + w1) + (w2 + w3);
        float2 a0 = __half22float2(*(__half2*)&r0.x), b0 = __half22float2(*(__half2*)&r0.y);
        float2 a1 = __half22float2(*(__half2*)&r1.x), b1 = __half22float2(*(__half2*)&r1.y);
        float2 a2 = __half22float2(*(__half2*)&r2.x), b2 = __half22float2(*(__half2*)&r2.y);
        float2 a3 = __half22float2(*(__half2*)&r3.x), b3 = __half22float2(*(__half2*)&r3.y);
        acc.x += w0 * a0.x + w1 * a1.x + w2 * a2.x + w3 * a3.x;
        acc.y += w0 * a0.y + w1 * a1.y + w2 * a2.y + w3 * a3.y;
        acc.z += w0 * b0.x + w1 * b1.x + w2 * b2.x + w3 * b3.x;
        acc.w += w0 * b0.y + w1 * b1.y + w2 * b2.y + w3 * b3.y;
    }
    for (; e < end; ++e) {
        int s = col[e];
        float wgt = __expf(lrelu(ss[s] + sd) - c);
        uint2 r0 = h2[s * 32 + l];
        float2 a0 = __half22float2(*(__half2*)&r0.x), b0 = __half22float2(*(__half2*)&r0.y);
        den += wgt;
        acc.x += wgt * a0.x; acc.y += wgt * a0.y;
        acc.z += wgt * b0.x; acc.w += wgt * b0.y;
    }
    float inv = 1.f / (den + 1e-16f);
    // lane l owns dims 4l..4l+3? No: uint2 lane layout = dims [4l..4l+3] as h0,h1 | h2,h3
    float2 bv0 = ((const float2*)bias)[2 * l];
    float2 bv1 = ((const float2*)bias)[2 * l + 1];
    float4 o;
    o.x = acc.x * inv + bv0.x;
    o.y = acc.y * inv + bv0.y;
    o.z = acc.z * inv + bv1.x;
    o.w = acc.w * inv + bv1.y;
    if (relu) {
        o.x = fmaxf(o.x, 0.f); o.y = fmaxf(o.y, 0.f);
        o.z = fmaxf(o.z, 0.f); o.w = fmaxf(o.w, 0.f);
    }
    ((float4*)out)[w * 32 + l] = o;
}

// ---------------- prediction head ----------------
__global__ void k_pred(const float* __restrict__ degree,
                       const float* __restrict__ Wp,
                       const float* __restrict__ bp,
                       float* __restrict__ out) {
    int v = (blockIdx.x * blockDim.x + threadIdx.x) >> 5;
    int l = threadIdx.x & 31;
    if (v >= NN) return;
    float4 xo = ((const float4*)g_x2o)[v * 32 + l];
    float4 xs = ((const float4*)g_x2s)[v * 32 + l];
    float dg = degree[v * 32 + l];
    int k0 = l * 4;
    float z0 = xo.x * Wp[(k0 + 0) * 2] + xo.y * Wp[(k0 + 1) * 2]
             + xo.z * Wp[(k0 + 2) * 2] + xo.w * Wp[(k0 + 3) * 2]
             + xs.x * Wp[(128 + k0 + 0) * 2] + xs.y * Wp[(128 + k0 + 1) * 2]
             + xs.z * Wp[(128 + k0 + 2) * 2] + xs.w * Wp[(128 + k0 + 3) * 2]
             + dg * Wp[(256 + l) * 2];
    float z1 = xo.x * Wp[(k0 + 0) * 2 + 1] + xo.y * Wp[(k0 + 1) * 2 + 1]
             + xo.z * Wp[(k0 + 2) * 2 + 1] + xo.w * Wp[(k0 + 3) * 2 + 1]
             + xs.x * Wp[(128 + k0 + 0) * 2 + 1] + xs.y * Wp[(128 + k0 + 1) * 2 + 1]
             + xs.z * Wp[(128 + k0 + 2) * 2 + 1] + xs.w * Wp[(128 + k0 + 3) * 2 + 1]
             + dg * Wp[(256 + l) * 2 + 1];
#pragma unroll
    for (int off = 16; off; off >>= 1) {
        z0 += __shfl_xor_sync(0xffffffffu, z0, off);
        z1 += __shfl_xor_sync(0xffffffffu, z1, off);
    }
    z0 += bp[0];
    z1 += bp[1];
    float mz = fmaxf(z0, z1);
    float e0 = __expf(z0 - mz), e1 = __expf(z1 - mz);
    float inv = 1.f / (e0 + e1);
    float a0 = e0 * inv, a1 = e1 * inv;
    float4 o;
    o.x = a0 * xo.x + a1 * xs.x;
    o.y = a0 * xo.y + a1 * xs.y;
    o.z = a0 * xo.z + a1 * xs.z;
    o.w = a0 * xo.w + a1 * xs.w;
    ((float4*)out)[v * 32 + l] = o;
}

// ---------------- host orchestration ----------------
static void build_csr(const int* ei, int gsel) {
    k_deg_init<<<(NN + 255) / 256, 256>>>();
    k_deg_count<<<(EDGES + 255) / 256, 256>>>(ei);
    k_scan_local<<<49, 1024>>>(gsel);
    k_scan_block<<<1, 64>>>();
    k_fill_self<<<49, 1024>>>(gsel);
    k_fill_edges<<<(EDGES + 255) / 256, 256>>>(ei, gsel);
}

static void run_conv(const float* Xext, int use_x1,
                     const float* W, const float* asrc, const float* adst,
                     const float* bias, int gsel, int out_sel, int relu, int slot) {
    k_gemm<<<(NN + GBM - 1) / GBM, 256>>>(Xext, use_x1, W, asrc, adst, slot);
    k_aggregate<<<NN / 8, 256>>>(gsel, out_sel, bias, relu, slot);
}

extern "C" void kernel_launch(void* const* d_in, const int* in_sizes, int n_in,
                              void* d_out, int out_size) {
    const float* x_o    = (const float*)d_in[0];
    const float* degree = (const float*)d_in[1];
    const int *ei_o, *ei_s;
    int base;
    if (in_sizes[2] == 2 * EDGES) {
        ei_o = (const int*)d_in[2];
        ei_s = (const int*)d_in[3];
        base = 4;
    } else {
        base = 2;
        ei_o = (const int*)d_in[20];
        ei_s = (const int*)d_in[21];
    }
    const float* W_o1 = (const float*)d_in[base + 0];
    const float* a_src_o1 = (const float*)d_in[base + 1];
    const float* a_dst_o1 = (const float*)d_in[base + 2];
    const float* b_o1 = (const float*)d_in[base + 3];
    const float* W_o2 = (const float*)d_in[base + 4];
    const float* a_src_o2 = (const float*)d_in[base + 5];
    const float* a_dst_o2 = (const float*)d_in[base + 6];
    const float* b_o2 = (const float*)d_in[base + 7];
    const float* W_s1 = (const float*)d_in[base + 8];
    const float* a_src_s1 = (const float*)d_in[base + 9];
    const float* a_dst_s1 = (const float*)d_in[base + 10];
    const float* b_s1 = (const float*)d_in[base + 11];
    const float* W_s2 = (const float*)d_in[base + 12];
    const float* a_src_s2 = (const float*)d_in[base + 13];
    const float* a_dst_s2 = (const float*)d_in[base + 14];
    const float* b_s2 = (const float*)d_in[base + 15];
    const float* W_pred = (const float*)d_in[base + 16];
    const float* b_pred = (const float*)d_in[base + 17];
    float* out = (float*)d_out;

    build_csr(ei_o, 0);
    run_conv(x_o, 0, W_o1, a_src_o1, a_dst_o1, b_o1, 0, 0, 1, 0);
    run_conv(nullptr, 1, W_o2, a_src_o2, a_dst_o2, b_o2, 0, 1, 0, 1);
    build_csr(ei_s, 1);
    run_conv(x_o, 0, W_s1, a_src_s1, a_dst_s1, b_s1, 1, 0, 1, 2);
    run_conv(nullptr, 1, W_s2, a_src_s2, a_dst_s2, b_s2, 1, 2, 0, 3);
    k_pred<<<NN / 8, 256>>>(degree, W_pred, b_pred, out);
}

// round 4
// speedup vs baseline: 1.6762x; 1.2577x over previous
#include <cuda_runtime.h>
#include <cuda_fp16.h>

#define NN 50000
#define EDGES 1000000
#define DD 128
#define TOTE (EDGES + NN)

// ---------------- scratch ----------------
__device__ __half g_h16[NN * DD];    // transformed features (fp16)
__device__ __half g_xin16[NN * DD];  // fp16 copy of x_o
__device__ __half g_a16[NN * DD];    // fp16 x1 (layer-2 GEMM input)
__device__ float g_x2o[NN * DD];
__device__ float g_x2s[NN * DD];
__device__ float g_ssrc[NN];
__device__ float g_sdst[NN];
__device__ unsigned g_gmax[8];
__device__ int   g_deg[NN];
__device__ int   g_fill[NN];
__device__ int   g_bsum[64];
__device__ int   g_boff[64];
__device__ int   g_rowptr_o[NN + 1];
__device__ int   g_rowptr_s[NN + 1];
__device__ int   g_col_o[TOTE];
__device__ int   g_col_s[TOTE];

__device__ __forceinline__ unsigned encf(float f) {
    unsigned u = __float_as_uint(f);
    return (u & 0x80000000u) ? ~u : (u | 0x80000000u);
}
__device__ __forceinline__ float decf(unsigned u) {
    return __uint_as_float((u & 0x80000000u) ? (u & 0x7fffffffu) : ~u);
}
__device__ __forceinline__ float lrelu(float z) { return z > 0.f ? z : 0.2f * z; }

// ---------------- fp32 -> fp16 input conversion ----------------
__global__ void k_tohalf(const float* __restrict__ x) {
    int i = blockIdx.x * blockDim.x + threadIdx.x;
    if (i < NN * DD / 4) {
        float4 v = ((const float4*)x)[i];
        uint2 p;
        __half2 h0 = __floats2half2_rn(v.x, v.y);
        __half2 h1 = __floats2half2_rn(v.z, v.w);
        p.x = *(unsigned*)&h0;
        p.y = *(unsigned*)&h1;
        ((uint2*)g_xin16)[i] = p;
    }
}

// ---------------- CSR build ----------------
__global__ void k_deg_init() {
    int i = blockIdx.x * blockDim.x + threadIdx.x;
    if (i < NN) g_deg[i] = 1;
    if (i < 8) g_gmax[i] = encf(-1e30f);
}

__global__ void k_deg_count(const int* __restrict__ ei) {
    int e = blockIdx.x * blockDim.x + threadIdx.x;
    if (e < EDGES) atomicAdd(&g_deg[ei[EDGES + e]], 1);
}

__global__ void k_scan_local(int gsel) {
    int* rowptr = gsel ? g_rowptr_s : g_rowptr_o;
    __shared__ int sh[1024];
    int tid = threadIdx.x;
    int idx = blockIdx.x * 1024 + tid;
    int v = (idx < NN) ? g_deg[idx] : 0;
    sh[tid] = v;
    __syncthreads();
    for (int off = 1; off < 1024; off <<= 1) {
        int t = (tid >= off) ? sh[tid - off] : 0;
        __syncthreads();
        sh[tid] += t;
        __syncthreads();
    }
    if (idx < NN) rowptr[idx] = sh[tid] - v;
    if (tid == 1023) g_bsum[blockIdx.x] = sh[tid];
}

__global__ void k_scan_block() {
    __shared__ int sh[64];
    int tid = threadIdx.x;
    int v = (tid < 49) ? g_bsum[tid] : 0;
    sh[tid] = v;
    __syncthreads();
    for (int off = 1; off < 64; off <<= 1) {
        int t = (tid >= off) ? sh[tid - off] : 0;
        __syncthreads();
        sh[tid] += t;
        __syncthreads();
    }
    g_boff[tid] = sh[tid] - v;
}

__global__ void k_fill_self(int gsel) {
    int* rowptr = gsel ? g_rowptr_s : g_rowptr_o;
    int* col = gsel ? g_col_s : g_col_o;
    int idx = blockIdx.x * 1024 + threadIdx.x;
    if (idx < NN) {
        int p = rowptr[idx] + g_boff[idx >> 10];
        rowptr[idx] = p;
        col[p] = idx;
        g_fill[idx] = p + 1;
    }
    if (idx == 0) rowptr[NN] = TOTE;
}

__global__ void k_fill_edges(const int* __restrict__ ei, int gsel) {
    int* col = gsel ? g_col_s : g_col_o;
    int e = blockIdx.x * blockDim.x + threadIdx.x;
    if (e < EDGES) {
        int s = ei[e];
        int d = ei[EDGES + e];
        int pos = atomicAdd(&g_fill[d], 1);
        col[pos] = s;
    }
}

// ---------------- HMMA GEMM 128x128x128 + fused scalars ----------------
#define APITCH 72   // halves per A smem row (64 + 8 pad)
#define BPITCH 136  // halves per B smem row (128 + 8 pad)

__device__ __forceinline__ void ldsm_x4(unsigned& r0, unsigned& r1, unsigned& r2, unsigned& r3,
                                        unsigned addr) {
    asm volatile("ldmatrix.sync.aligned.m8n8.x4.shared.b16 {%0,%1,%2,%3}, [%4];"
                 : "=r"(r0), "=r"(r1), "=r"(r2), "=r"(r3) : "r"(addr));
}
__device__ __forceinline__ void ldsm_x4_t(unsigned& r0, unsigned& r1, unsigned& r2, unsigned& r3,
                                          unsigned addr) {
    asm volatile("ldmatrix.sync.aligned.m8n8.x4.trans.shared.b16 {%0,%1,%2,%3}, [%4];"
                 : "=r"(r0), "=r"(r1), "=r"(r2), "=r"(r3) : "r"(addr));
}
__device__ __forceinline__ void hmma(float* d, unsigned a0, unsigned a1, unsigned a2, unsigned a3,
                                     unsigned b0, unsigned b1) {
    asm volatile("mma.sync.aligned.m16n8k16.row.col.f32.f16.f16.f32 "
                 "{%0,%1,%2,%3}, {%4,%5,%6,%7}, {%8,%9}, {%0,%1,%2,%3};"
                 : "+f"(d[0]), "+f"(d[1]), "+f"(d[2]), "+f"(d[3])
                 : "r"(a0), "r"(a1), "r"(a2), "r"(a3), "r"(b0), "r"(b1));
}

__global__ __launch_bounds__(256, 2) void k_gemm(
    const __half* __restrict__ A,          // [NN,128] fp16
    const float* __restrict__ W,           // [128,128] fp32
    const float* __restrict__ a_src, const float* __restrict__ a_dst,
    int slot)
{
    __shared__ __half Ash[128 * APITCH];
    __shared__ __half Bsh[64 * BPITCH];
    __shared__ float s_red[8][2];
    int tid = threadIdx.x;
    int l = tid & 31;
    int wid = tid >> 5;
    int row0 = blockIdx.x * 128;

    float acc[16][4];
#pragma unroll
    for (int j = 0; j < 16; ++j)
#pragma unroll
        for (int q = 0; q < 4; ++q) acc[j][q] = 0.f;

    // ldmatrix base addresses (per lane)
    int arow = wid * 16 + (l & 15);
    int acolo = (l >> 4) * 8;
    unsigned a_base = (unsigned)__cvta_generic_to_shared(&Ash[arow * APITCH + acolo]);
    int brow = l & 15;
    int bcolo = (l >> 4) * 8;
    unsigned b_base = (unsigned)__cvta_generic_to_shared(&Bsh[brow * BPITCH + bcolo]);

    for (int kb = 0; kb < 2; ++kb) {
        // load A tile: 128 rows x 64 halves (rows row0.., cols kb*64..)
#pragma unroll
        for (int t = 0; t < 4; ++t) {
            int i = tid + t * 256;             // 0..1023
            int r = i >> 3;
            int c = i & 7;                     // uint4 index (8 halves)
            uint4 v = make_uint4(0u, 0u, 0u, 0u);
            if (row0 + r < NN)
                v = *(const uint4*)&A[(row0 + r) * DD + kb * 64 + c * 8];
            *(uint4*)&Ash[r * APITCH + c * 8] = v;
        }
        // load B tile: W rows kb*64..+63, all 128 cols; convert fp32->fp16
#pragma unroll
        for (int t = 0; t < 8; ++t) {
            int i = tid + t * 256;             // 0..2047
            int r = i >> 5;
            int c4 = i & 31;
            float4 v = *(const float4*)&W[(kb * 64 + r) * DD + c4 * 4];
            __half2 h0 = __floats2half2_rn(v.x, v.y);
            __half2 h1 = __floats2half2_rn(v.z, v.w);
            uint2 p;
            p.x = *(unsigned*)&h0;
            p.y = *(unsigned*)&h1;
            *(uint2*)&Bsh[r * BPITCH + c4 * 4] = p;
        }
        __syncthreads();
#pragma unroll
        for (int ks = 0; ks < 4; ++ks) {
            unsigned a0, a1, a2, a3;
            ldsm_x4(a0, a1, a2, a3, a_base + (unsigned)(ks * 16 * 2));
#pragma unroll
            for (int np = 0; np < 8; ++np) {
                unsigned b0, b1, b2, b3;
                ldsm_x4_t(b0, b1, b2, b3,
                          b_base + (unsigned)((ks * 16 * BPITCH + np * 16) * 2));
                hmma(acc[2 * np], a0, a1, a2, a3, b0, b1);
                hmma(acc[2 * np + 1], a0, a1, a2, a3, b2, b3);
            }
        }
        __syncthreads();
    }

    // ---- epilogue: write h fp16, fused s_src/s_dst ----
    int g = l >> 2, tg = l & 3;
    int r0g = row0 + wid * 16 + g;
    int r1g = r0g + 8;
    float ps0 = 0.f, pd0 = 0.f, ps1 = 0.f, pd1 = 0.f;
#pragma unroll
    for (int j = 0; j < 16; ++j) {
        int colc = j * 8 + tg * 2;
        float2 asv = *(const float2*)&a_src[colc];
        float2 adv = *(const float2*)&a_dst[colc];
        ps0 += acc[j][0] * asv.x + acc[j][1] * asv.y;
        pd0 += acc[j][0] * adv.x + acc[j][1] * adv.y;
        ps1 += acc[j][2] * asv.x + acc[j][3] * asv.y;
        pd1 += acc[j][2] * adv.x + acc[j][3] * adv.y;
        if (r0g < NN)
            *(__half2*)&g_h16[r0g * DD + colc] = __floats2half2_rn(acc[j][0], acc[j][1]);
        if (r1g < NN)
            *(__half2*)&g_h16[r1g * DD + colc] = __floats2half2_rn(acc[j][2], acc[j][3]);
    }
    // quad reduce (over tg)
#pragma unroll
    for (int off = 1; off < 4; off <<= 1) {
        ps0 += __shfl_xor_sync(0xffffffffu, ps0, off);
        pd0 += __shfl_xor_sync(0xffffffffu, pd0, off);
        ps1 += __shfl_xor_sync(0xffffffffu, ps1, off);
        pd1 += __shfl_xor_sync(0xffffffffu, pd1, off);
    }
    float lms = -1e30f, lmd = -1e30f;
    if (tg == 0) {
        if (r0g < NN) {
            g_ssrc[r0g] = ps0; g_sdst[r0g] = pd0;
            lms = ps0; lmd = pd0;
        }
        if (r1g < NN) {
            g_ssrc[r1g] = ps1; g_sdst[r1g] = pd1;
            lms = fmaxf(lms, ps1); lmd = fmaxf(lmd, pd1);
        }
    }
#pragma unroll
    for (int off = 16; off; off >>= 1) {
        lms = fmaxf(lms, __shfl_xor_sync(0xffffffffu, lms, off));
        lmd = fmaxf(lmd, __shfl_xor_sync(0xffffffffu, lmd, off));
    }
    if (l == 0) { s_red[wid][0] = lms; s_red[wid][1] = lmd; }
    __syncthreads();
    if (tid == 0) {
        float ms = s_red[0][0], md = s_red[0][1];
#pragma unroll
        for (int i = 1; i < 8; ++i) {
            ms = fmaxf(ms, s_red[i][0]);
            md = fmaxf(md, s_red[i][1]);
        }
        atomicMax(&g_gmax[2 * slot], encf(ms));
        atomicMax(&g_gmax[2 * slot + 1], encf(md));
    }
}

// ---------------- single-pass softmax aggregate (warp per dst, fp16 gather) ----------------
__global__ __launch_bounds__(256) void k_aggregate(int gsel, int out_sel,
                                                   const float* __restrict__ bias,
                                                   int slot) {
    const int* __restrict__ rowptr = gsel ? g_rowptr_s : g_rowptr_o;
    const int* __restrict__ col    = gsel ? g_col_s    : g_col_o;
    int w = (blockIdx.x * blockDim.x + threadIdx.x) >> 5;
    int l = threadIdx.x & 31;
    if (w >= NN) return;
    float c = lrelu(decf(g_gmax[2 * slot]) + decf(g_gmax[2 * slot + 1]));
    int beg = rowptr[w];
    int end = rowptr[w + 1];
    float sd = g_sdst[w];
    const uint2* __restrict__ h2 = (const uint2*)g_h16;
    const float* __restrict__ ss = g_ssrc;
    float4 acc = make_float4(0.f, 0.f, 0.f, 0.f);
    float den = 0.f;
    int e = beg;
    for (; e + 4 <= end; e += 4) {
        int s0 = col[e], s1 = col[e + 1], s2 = col[e + 2], s3 = col[e + 3];
        float w0 = __expf(lrelu(ss[s0] + sd) - c);
        float w1 = __expf(lrelu(ss[s1] + sd) - c);
        float w2 = __expf(lrelu(ss[s2] + sd) - c);
        float w3 = __expf(lrelu(ss[s3] + sd) - c);
        uint2 r0 = h2[s0 * 32 + l];
        uint2 r1 = h2[s1 * 32 + l];
        uint2 r2 = h2[s2 * 32 + l];
        uint2 r3 = h2[s3 * 32 + l];
        den += (w0 + w1) + (w2 + w3);
        float2 a0 = __half22float2(*(__half2*)&r0.x), b0 = __half22float2(*(__half2*)&r0.y);
        float2 a1 = __half22float2(*(__half2*)&r1.x), b1 = __half22float2(*(__half2*)&r1.y);
        float2 a2 = __half22float2(*(__half2*)&r2.x), b2 = __half22float2(*(__half2*)&r2.y);
        float2 a3 = __half22float2(*(__half2*)&r3.x), b3 = __half22float2(*(__half2*)&r3.y);
        acc.x += w0 * a0.x + w1 * a1.x + w2 * a2.x + w3 * a3.x;
        acc.y += w0 * a0.y + w1 * a1.y + w2 * a2.y + w3 * a3.y;
        acc.z += w0 * b0.x + w1 * b1.x + w2 * b2.x + w3 * b3.x;
        acc.w += w0 * b0.y + w1 * b1.y + w2 * b2.y + w3 * b3.y;
    }
    for (; e < end; ++e) {
        int s = col[e];
        float wgt = __expf(lrelu(ss[s] + sd) - c);
        uint2 r0 = h2[s * 32 + l];
        float2 a0 = __half22float2(*(__half2*)&r0.x), b0 = __half22float2(*(__half2*)&r0.y);
        den += wgt;
        acc.x += wgt * a0.x; acc.y += wgt * a0.y;
        acc.z += wgt * b0.x; acc.w += wgt * b0.y;
    }
    float inv = 1.f / (den + 1e-16f);
    float2 bv0 = ((const float2*)bias)[2 * l];
    float2 bv1 = ((const float2*)bias)[2 * l + 1];
    float4 o;
    o.x = acc.x * inv + bv0.x;
    o.y = acc.y * inv + bv0.y;
    o.z = acc.z * inv + bv1.x;
    o.w = acc.w * inv + bv1.y;
    if (out_sel == 0) {
        // relu + fp16 store (input to next GEMM)
        o.x = fmaxf(o.x, 0.f); o.y = fmaxf(o.y, 0.f);
        o.z = fmaxf(o.z, 0.f); o.w = fmaxf(o.w, 0.f);
        __half2 h0 = __floats2half2_rn(o.x, o.y);
        __half2 h1 = __floats2half2_rn(o.z, o.w);
        uint2 p;
        p.x = *(unsigned*)&h0;
        p.y = *(unsigned*)&h1;
        ((uint2*)g_a16)[w * 32 + l] = p;
    } else {
        float* out = (out_sel == 1) ? g_x2o : g_x2s;
        ((float4*)out)[w * 32 + l] = o;
    }
}

// ---------------- prediction head ----------------
__global__ void k_pred(const float* __restrict__ degree,
                       const float* __restrict__ Wp,
                       const float* __restrict__ bp,
                       float* __restrict__ out) {
    int v = (blockIdx.x * blockDim.x + threadIdx.x) >> 5;
    int l = threadIdx.x & 31;
    if (v >= NN) return;
    float4 xo = ((const float4*)g_x2o)[v * 32 + l];
    float4 xs = ((const float4*)g_x2s)[v * 32 + l];
    float dg = degree[v * 32 + l];
    int k0 = l * 4;
    float z0 = xo.x * Wp[(k0 + 0) * 2] + xo.y * Wp[(k0 + 1) * 2]
             + xo.z * Wp[(k0 + 2) * 2] + xo.w * Wp[(k0 + 3) * 2]
             + xs.x * Wp[(128 + k0 + 0) * 2] + xs.y * Wp[(128 + k0 + 1) * 2]
             + xs.z * Wp[(128 + k0 + 2) * 2] + xs.w * Wp[(128 + k0 + 3) * 2]
             + dg * Wp[(256 + l) * 2];
    float z1 = xo.x * Wp[(k0 + 0) * 2 + 1] + xo.y * Wp[(k0 + 1) * 2 + 1]
             + xo.z * Wp[(k0 + 2) * 2 + 1] + xo.w * Wp[(k0 + 3) * 2 + 1]
             + xs.x * Wp[(128 + k0 + 0) * 2 + 1] + xs.y * Wp[(128 + k0 + 1) * 2 + 1]
             + xs.z * Wp[(128 + k0 + 2) * 2 + 1] + xs.w * Wp[(128 + k0 + 3) * 2 + 1]
             + dg * Wp[(256 + l) * 2 + 1];
#pragma unroll
    for (int off = 16; off; off >>= 1) {
        z0 += __shfl_xor_sync(0xffffffffu, z0, off);
        z1 += __shfl_xor_sync(0xffffffffu, z1, off);
    }
    z0 += bp[0];
    z1 += bp[1];
    float mz = fmaxf(z0, z1);
    float e0 = __expf(z0 - mz), e1 = __expf(z1 - mz);
    float inv = 1.f / (e0 + e1);
    float a0 = e0 * inv, a1 = e1 * inv;
    float4 o;
    o.x = a0 * xo.x + a1 * xs.x;
    o.y = a0 * xo.y + a1 * xs.y;
    o.z = a0 * xo.z + a1 * xs.z;
    o.w = a0 * xo.w + a1 * xs.w;
    ((float4*)out)[v * 32 + l] = o;
}

// ---------------- host orchestration ----------------
static void build_csr(const int* ei, int gsel) {
    k_deg_init<<<(NN + 255) / 256, 256>>>();
    k_deg_count<<<(EDGES + 255) / 256, 256>>>(ei);
    k_scan_local<<<49, 1024>>>(gsel);
    k_scan_block<<<1, 64>>>();
    k_fill_self<<<49, 1024>>>(gsel);
    k_fill_edges<<<(EDGES + 255) / 256, 256>>>(ei, gsel);
}

static const __half* dev_xin16() {
    const __half* p = nullptr;
    cudaGetSymbolAddress((void**)&p, g_xin16);
    return p;
}
static const __half* dev_a16() {
    const __half* p = nullptr;
    cudaGetSymbolAddress((void**)&p, g_a16);
    return p;
}

static void run_conv(const __half* A,
                     const float* W, const float* asrc, const float* adst,
                     const float* bias, int gsel, int out_sel, int slot) {
    k_gemm<<<(NN + 127) / 128, 256>>>(A, W, asrc, adst, slot);
    k_aggregate<<<NN / 8, 256>>>(gsel, out_sel, bias, slot);
}

extern "C" void kernel_launch(void* const* d_in, const int* in_sizes, int n_in,
                              void* d_out, int out_size) {
    const float* x_o    = (const float*)d_in[0];
    const float* degree = (const float*)d_in[1];
    const int *ei_o, *ei_s;
    int base;
    if (in_sizes[2] == 2 * EDGES) {
        ei_o = (const int*)d_in[2];
        ei_s = (const int*)d_in[3];
        base = 4;
    } else {
        base = 2;
        ei_o = (const int*)d_in[20];
        ei_s = (const int*)d_in[21];
    }
    const float* W_o1 = (const float*)d_in[base + 0];
    const float* a_src_o1 = (const float*)d_in[base + 1];
    const float* a_dst_o1 = (const float*)d_in[base + 2];
    const float* b_o1 = (const float*)d_in[base + 3];
    const float* W_o2 = (const float*)d_in[base + 4];
    const float* a_src_o2 = (const float*)d_in[base + 5];
    const float* a_dst_o2 = (const float*)d_in[base + 6];
    const float* b_o2 = (const float*)d_in[base + 7];
    const float* W_s1 = (const float*)d_in[base + 8];
    const float* a_src_s1 = (const float*)d_in[base + 9];
    const float* a_dst_s1 = (const float*)d_in[base + 10];
    const float* b_s1 = (const float*)d_in[base + 11];
    const float* W_s2 = (const float*)d_in[base + 12];
    const float* a_src_s2 = (const float*)d_in[base + 13];
    const float* a_dst_s2 = (const float*)d_in[base + 14];
    const float* b_s2 = (const float*)d_in[base + 15];
    const float* W_pred = (const float*)d_in[base + 16];
    const float* b_pred = (const float*)d_in[base + 17];
    float* out = (float*)d_out;

    const __half* xin = dev_xin16();
    const __half* a16 = dev_a16();

    k_tohalf<<<(NN * DD / 4 + 255) / 256, 256>>>(x_o);

    build_csr(ei_o, 0);
    run_conv(xin, W_o1, a_src_o1, a_dst_o1, b_o1, 0, 0, 0);
    run_conv(a16, W_o2, a_src_o2, a_dst_o2, b_o2, 0, 1, 1);
    build_csr(ei_s, 1);
    run_conv(xin, W_s1, a_src_s1, a_dst_s1, b_s1, 1, 0, 2);
    run_conv(a16, W_s2, a_src_s2, a_dst_s2, b_s2, 1, 2, 3);
    k_pred<<<NN / 8, 256>>>(degree, W_pred, b_pred, out);
}

// round 5
// speedup vs baseline: 1.8205x; 1.0861x over previous
#include <cuda_runtime.h>
#include <cuda_fp16.h>

#define NN 50000
#define EDGES 1000000
#define DD 128
#define TOTE (EDGES + NN)

// ---------------- scratch ----------------
__device__ __half g_h16[2][NN * DD];   // per-branch transformed features
__device__ __half g_xin16[NN * DD];    // fp16 x_o
__device__ __half g_a16[2][NN * DD];   // per-branch fp16 x1
__device__ float g_x2o[NN * DD];
__device__ float g_x2s[NN * DD];
__device__ float g_ssrc[2 * NN];
__device__ float g_sdst[2 * NN];
__device__ unsigned g_gmax[8];
__device__ int   g_deg[2 * NN];
__device__ int   g_fill[2 * NN];
__device__ int   g_bsum[128];
__device__ int   g_boff[128];
__device__ int   g_rowptr[2 * (NN + 1)];
__device__ int   g_col[2 * TOTE];

__device__ __forceinline__ unsigned encf(float f) {
    unsigned u = __float_as_uint(f);
    return (u & 0x80000000u) ? ~u : (u | 0x80000000u);
}
__device__ __forceinline__ float decf(unsigned u) {
    return __uint_as_float((u & 0x80000000u) ? (u & 0x7fffffffu) : ~u);
}
__device__ __forceinline__ float lrelu(float z) { return z > 0.f ? z : 0.2f * z; }

// ---------------- prep: tohalf + deg/gmax init ----------------
__global__ void k_prep(const float* __restrict__ x) {
    int i = blockIdx.x * blockDim.x + threadIdx.x;
    if (i < NN * DD / 4) {
        float4 v = ((const float4*)x)[i];
        uint2 p;
        __half2 h0 = __floats2half2_rn(v.x, v.y);
        __half2 h1 = __floats2half2_rn(v.z, v.w);
        p.x = *(unsigned*)&h0;
        p.y = *(unsigned*)&h1;
        ((uint2*)g_xin16)[i] = p;
    }
    if (i < 2 * NN) g_deg[i] = 1;     // self loops, both graphs
    if (i < 8) g_gmax[i] = encf(-1e30f);
}

// ---------------- CSR build (both graphs fused) ----------------
__global__ void k_deg_count(const int* __restrict__ ei_o, const int* __restrict__ ei_s) {
    int e = blockIdx.x * blockDim.x + threadIdx.x;
    if (e < 2 * EDGES) {
        int g = (e >= EDGES);
        int le = e - g * EDGES;
        const int* ei = g ? ei_s : ei_o;
        atomicAdd(&g_deg[g * NN + ei[EDGES + le]], 1);
    }
}

__global__ void k_scan_local() {
    __shared__ int sh[1024];
    int tid = threadIdx.x;
    int g = (blockIdx.x >= 49);
    int lb = blockIdx.x - g * 49;
    int idx = lb * 1024 + tid;
    int v = (idx < NN) ? g_deg[g * NN + idx] : 0;
    sh[tid] = v;
    __syncthreads();
    for (int off = 1; off < 1024; off <<= 1) {
        int t = (tid >= off) ? sh[tid - off] : 0;
        __syncthreads();
        sh[tid] += t;
        __syncthreads();
    }
    if (idx < NN) g_rowptr[g * (NN + 1) + idx] = sh[tid] - v;
    if (tid == 1023) g_bsum[g * 64 + lb] = sh[tid];
}

__global__ void k_scan_block() {
    // 128 threads: two independent 64-wide scans
    __shared__ int sh[128];
    int tid = threadIdx.x;
    int lt = tid & 63;
    int v = (lt < 49) ? g_bsum[tid] : 0;
    sh[tid] = v;
    __syncthreads();
    for (int off = 1; off < 64; off <<= 1) {
        int t = (lt >= off) ? sh[tid - off] : 0;
        __syncthreads();
        sh[tid] += t;
        __syncthreads();
    }
    g_boff[tid] = sh[tid] - v;
}

__global__ void k_fill_self() {
    int g = (blockIdx.x >= 49);
    int lb = blockIdx.x - g * 49;
    int idx = lb * 1024 + threadIdx.x;
    if (idx < NN) {
        int p = g_rowptr[g * (NN + 1) + idx] + g_boff[g * 64 + (idx >> 10)];
        g_rowptr[g * (NN + 1) + idx] = p;
        g_col[g * TOTE + p] = idx;
        g_fill[g * NN + idx] = p + 1;
    }
    if (idx == 0) g_rowptr[g * (NN + 1) + NN] = TOTE;
}

__global__ void k_fill_edges(const int* __restrict__ ei_o, const int* __restrict__ ei_s) {
    int e = blockIdx.x * blockDim.x + threadIdx.x;
    if (e < 2 * EDGES) {
        int g = (e >= EDGES);
        int le = e - g * EDGES;
        const int* ei = g ? ei_s : ei_o;
        int s = ei[le];
        int d = ei[EDGES + le];
        int pos = atomicAdd(&g_fill[g * NN + d], 1);
        g_col[g * TOTE + pos] = s;
    }
}

// ---------------- HMMA GEMM 128x128x128, both branches (grid.y) ----------------
#define APITCH 72
#define BPITCH 136

__device__ __forceinline__ void ldsm_x4(unsigned& r0, unsigned& r1, unsigned& r2, unsigned& r3,
                                        unsigned addr) {
    asm volatile("ldmatrix.sync.aligned.m8n8.x4.shared.b16 {%0,%1,%2,%3}, [%4];"
                 : "=r"(r0), "=r"(r1), "=r"(r2), "=r"(r3) : "r"(addr));
}
__device__ __forceinline__ void ldsm_x4_t(unsigned& r0, unsigned& r1, unsigned& r2, unsigned& r3,
                                          unsigned addr) {
    asm volatile("ldmatrix.sync.aligned.m8n8.x4.trans.shared.b16 {%0,%1,%2,%3}, [%4];"
                 : "=r"(r0), "=r"(r1), "=r"(r2), "=r"(r3) : "r"(addr));
}
__device__ __forceinline__ void hmma(float* d, unsigned a0, unsigned a1, unsigned a2, unsigned a3,
                                     unsigned b0, unsigned b1) {
    asm volatile("mma.sync.aligned.m16n8k16.row.col.f32.f16.f16.f32 "
                 "{%0,%1,%2,%3}, {%4,%5,%6,%7}, {%8,%9}, {%0,%1,%2,%3};"
                 : "+f"(d[0]), "+f"(d[1]), "+f"(d[2]), "+f"(d[3])
                 : "r"(a0), "r"(a1), "r"(a2), "r"(a3), "r"(b0), "r"(b1));
}

__global__ __launch_bounds__(256, 2) void k_gemm(
    int layer,
    const float* __restrict__ W0, const float* __restrict__ W1,
    const float* __restrict__ as0, const float* __restrict__ as1,
    const float* __restrict__ ad0, const float* __restrict__ ad1)
{
    int b = blockIdx.y;
    const __half* __restrict__ A = (layer == 0) ? g_xin16 : g_a16[b];
    const float* __restrict__ W = b ? W1 : W0;
    const float* __restrict__ a_src = b ? as1 : as0;
    const float* __restrict__ a_dst = b ? ad1 : ad0;
    int slot = layer * 2 + b;
    __half* __restrict__ H = g_h16[b];
    float* __restrict__ ssrc = g_ssrc + b * NN;
    float* __restrict__ sdst = g_sdst + b * NN;

    __shared__ __half Ash[128 * APITCH];
    __shared__ __half Bsh[64 * BPITCH];
    __shared__ float s_red[8][2];
    int tid = threadIdx.x;
    int l = tid & 31;
    int wid = tid >> 5;
    int row0 = blockIdx.x * 128;

    float acc[16][4];
#pragma unroll
    for (int j = 0; j < 16; ++j)
#pragma unroll
        for (int q = 0; q < 4; ++q) acc[j][q] = 0.f;

    int arow = wid * 16 + (l & 15);
    int acolo = (l >> 4) * 8;
    unsigned a_base = (unsigned)__cvta_generic_to_shared(&Ash[arow * APITCH + acolo]);
    int brow = l & 15;
    int bcolo = (l >> 4) * 8;
    unsigned b_base = (unsigned)__cvta_generic_to_shared(&Bsh[brow * BPITCH + bcolo]);

    for (int kb = 0; kb < 2; ++kb) {
#pragma unroll
        for (int t = 0; t < 4; ++t) {
            int i = tid + t * 256;
            int r = i >> 3;
            int c = i & 7;
            uint4 v = make_uint4(0u, 0u, 0u, 0u);
            if (row0 + r < NN)
                v = *(const uint4*)&A[(row0 + r) * DD + kb * 64 + c * 8];
            *(uint4*)&Ash[r * APITCH + c * 8] = v;
        }
#pragma unroll
        for (int t = 0; t < 8; ++t) {
            int i = tid + t * 256;
            int r = i >> 5;
            int c4 = i & 31;
            float4 v = *(const float4*)&W[(kb * 64 + r) * DD + c4 * 4];
            __half2 h0 = __floats2half2_rn(v.x, v.y);
            __half2 h1 = __floats2half2_rn(v.z, v.w);
            uint2 p;
            p.x = *(unsigned*)&h0;
            p.y = *(unsigned*)&h1;
            *(uint2*)&Bsh[r * BPITCH + c4 * 4] = p;
        }
        __syncthreads();
#pragma unroll
        for (int ks = 0; ks < 4; ++ks) {
            unsigned a0, a1, a2, a3;
            ldsm_x4(a0, a1, a2, a3, a_base + (unsigned)(ks * 16 * 2));
#pragma unroll
            for (int np = 0; np < 8; ++np) {
                unsigned b0, b1, b2, b3;
                ldsm_x4_t(b0, b1, b2, b3,
                          b_base + (unsigned)((ks * 16 * BPITCH + np * 16) * 2));
                hmma(acc[2 * np], a0, a1, a2, a3, b0, b1);
                hmma(acc[2 * np + 1], a0, a1, a2, a3, b2, b3);
            }
        }
        __syncthreads();
    }

    // epilogue
    int g = l >> 2, tg = l & 3;
    int r0g = row0 + wid * 16 + g;
    int r1g = r0g + 8;
    float ps0 = 0.f, pd0 = 0.f, ps1 = 0.f, pd1 = 0.f;
#pragma unroll
    for (int j = 0; j < 16; ++j) {
        int colc = j * 8 + tg * 2;
        float2 asv = *(const float2*)&a_src[colc];
        float2 adv = *(const float2*)&a_dst[colc];
        ps0 += acc[j][0] * asv.x + acc[j][1] * asv.y;
        pd0 += acc[j][0] * adv.x + acc[j][1] * adv.y;
        ps1 += acc[j][2] * asv.x + acc[j][3] * asv.y;
        pd1 += acc[j][2] * adv.x + acc[j][3] * adv.y;
        if (r0g < NN)
            *(__half2*)&H[r0g * DD + colc] = __floats2half2_rn(acc[j][0], acc[j][1]);
        if (r1g < NN)
            *(__half2*)&H[r1g * DD + colc] = __floats2half2_rn(acc[j][2], acc[j][3]);
    }
#pragma unroll
    for (int off = 1; off < 4; off <<= 1) {
        ps0 += __shfl_xor_sync(0xffffffffu, ps0, off);
        pd0 += __shfl_xor_sync(0xffffffffu, pd0, off);
        ps1 += __shfl_xor_sync(0xffffffffu, ps1, off);
        pd1 += __shfl_xor_sync(0xffffffffu, pd1, off);
    }
    float lms = -1e30f, lmd = -1e30f;
    if (tg == 0) {
        if (r0g < NN) {
            ssrc[r0g] = ps0; sdst[r0g] = pd0;
            lms = ps0; lmd = pd0;
        }
        if (r1g < NN) {
            ssrc[r1g] = ps1; sdst[r1g] = pd1;
            lms = fmaxf(lms, ps1); lmd = fmaxf(lmd, pd1);
        }
    }
#pragma unroll
    for (int off = 16; off; off >>= 1) {
        lms = fmaxf(lms, __shfl_xor_sync(0xffffffffu, lms, off));
        lmd = fmaxf(lmd, __shfl_xor_sync(0xffffffffu, lmd, off));
    }
    if (l == 0) { s_red[wid][0] = lms; s_red[wid][1] = lmd; }
    __syncthreads();
    if (tid == 0) {
        float ms = s_red[0][0], md = s_red[0][1];
#pragma unroll
        for (int i = 1; i < 8; ++i) {
            ms = fmaxf(ms, s_red[i][0]);
            md = fmaxf(md, s_red[i][1]);
        }
        atomicMax(&g_gmax[2 * slot], encf(ms));
        atomicMax(&g_gmax[2 * slot + 1], encf(md));
    }
}

// ---------------- softmax aggregate, both branches (grid.y) ----------------
__global__ __launch_bounds__(256) void k_aggregate(int layer,
                                                   const float* __restrict__ bias0,
                                                   const float* __restrict__ bias1) {
    int b = blockIdx.y;
    const int* __restrict__ rowptr = g_rowptr + b * (NN + 1);
    const int* __restrict__ col    = g_col + b * TOTE;
    const float* __restrict__ bias = b ? bias1 : bias0;
    int slot = layer * 2 + b;
    int w = (blockIdx.x * blockDim.x + threadIdx.x) >> 5;
    int l = threadIdx.x & 31;
    if (w >= NN) return;
    float c = lrelu(decf(g_gmax[2 * slot]) + decf(g_gmax[2 * slot + 1]));
    int beg = rowptr[w];
    int end = rowptr[w + 1];
    float sd = g_sdst[b * NN + w];
    const uint2* __restrict__ h2 = (const uint2*)g_h16[b];
    const float* __restrict__ ss = g_ssrc + b * NN;
    float4 acc = make_float4(0.f, 0.f, 0.f, 0.f);
    float den = 0.f;
    int e = beg;
    for (; e + 4 <= end; e += 4) {
        int s0 = col[e], s1 = col[e + 1], s2 = col[e + 2], s3 = col[e + 3];
        float w0 = __expf(lrelu(ss[s0] + sd) - c);
        float w1 = __expf(lrelu(ss[s1] + sd) - c);
        float w2 = __expf(lrelu(ss[s2] + sd) - c);
        float w3 = __expf(lrelu(ss[s3] + sd) - c);
        uint2 r0 = h2[s0 * 32 + l];
        uint2 r1 = h2[s1 * 32 + l];
        uint2 r2 = h2[s2 * 32 + l];
        uint2 r3 = h2[s3 * 32 + l];
        den += (w0 + w1) + (w2 + w3);
        float2 a0 = __half22float2(*(__half2*)&r0.x), b0 = __half22float2(*(__half2*)&r0.y);
        float2 a1 = __half22float2(*(__half2*)&r1.x), b1 = __half22float2(*(__half2*)&r1.y);
        float2 a2 = __half22float2(*(__half2*)&r2.x), b2 = __half22float2(*(__half2*)&r2.y);
        float2 a3 = __half22float2(*(__half2*)&r3.x), b3 = __half22float2(*(__half2*)&r3.y);
        acc.x += w0 * a0.x + w1 * a1.x + w2 * a2.x + w3 * a3.x;
        acc.y += w0 * a0.y + w1 * a1.y + w2 * a2.y + w3 * a3.y;
        acc.z += w0 * b0.x + w1 * b1.x + w2 * b2.x + w3 * b3.x;
        acc.w += w0 * b0.y + w1 * b1.y + w2 * b2.y + w3 * b3.y;
    }
    for (; e < end; ++e) {
        int s = col[e];
        float wgt = __expf(lrelu(ss[s] + sd) - c);
        uint2 r0 = h2[s * 32 + l];
        float2 a0 = __half22float2(*(__half2*)&r0.x), b0 = __half22float2(*(__half2*)&r0.y);
        den += wgt;
        acc.x += wgt * a0.x; acc.y += wgt * a0.y;
        acc.z += wgt * b0.x; acc.w += wgt * b0.y;
    }
    float inv = 1.f / (den + 1e-16f);
    float2 bv0 = ((const float2*)bias)[2 * l];
    float2 bv1 = ((const float2*)bias)[2 * l + 1];
    float4 o;
    o.x = acc.x * inv + bv0.x;
    o.y = acc.y * inv + bv0.y;
    o.z = acc.z * inv + bv1.x;
    o.w = acc.w * inv + bv1.y;
    if (layer == 0) {
        o.x = fmaxf(o.x, 0.f); o.y = fmaxf(o.y, 0.f);
        o.z = fmaxf(o.z, 0.f); o.w = fmaxf(o.w, 0.f);
        __half2 h0 = __floats2half2_rn(o.x, o.y);
        __half2 h1 = __floats2half2_rn(o.z, o.w);
        uint2 p;
        p.x = *(unsigned*)&h0;
        p.y = *(unsigned*)&h1;
        ((uint2*)g_a16[b])[w * 32 + l] = p;
    } else {
        float* out = b ? g_x2s : g_x2o;
        ((float4*)out)[w * 32 + l] = o;
    }
}

// ---------------- prediction head ----------------
__global__ void k_pred(const float* __restrict__ degree,
                       const float* __restrict__ Wp,
                       const float* __restrict__ bp,
                       float* __restrict__ out) {
    int v = (blockIdx.x * blockDim.x + threadIdx.x) >> 5;
    int l = threadIdx.x & 31;
    if (v >= NN) return;
    float4 xo = ((const float4*)g_x2o)[v * 32 + l];
    float4 xs = ((const float4*)g_x2s)[v * 32 + l];
    float dg = degree[v * 32 + l];
    int k0 = l * 4;
    float z0 = xo.x * Wp[(k0 + 0) * 2] + xo.y * Wp[(k0 + 1) * 2]
             + xo.z * Wp[(k0 + 2) * 2] + xo.w * Wp[(k0 + 3) * 2]
             + xs.x * Wp[(128 + k0 + 0) * 2] + xs.y * Wp[(128 + k0 + 1) * 2]
             + xs.z * Wp[(128 + k0 + 2) * 2] + xs.w * Wp[(128 + k0 + 3) * 2]
             + dg * Wp[(256 + l) * 2];
    float z1 = xo.x * Wp[(k0 + 0) * 2 + 1] + xo.y * Wp[(k0 + 1) * 2 + 1]
             + xo.z * Wp[(k0 + 2) * 2 + 1] + xo.w * Wp[(k0 + 3) * 2 + 1]
             + xs.x * Wp[(128 + k0 + 0) * 2 + 1] + xs.y * Wp[(128 + k0 + 1) * 2 + 1]
             + xs.z * Wp[(128 + k0 + 2) * 2 + 1] + xs.w * Wp[(128 + k0 + 3) * 2 + 1]
             + dg * Wp[(256 + l) * 2 + 1];
#pragma unroll
    for (int off = 16; off; off >>= 1) {
        z0 += __shfl_xor_sync(0xffffffffu, z0, off);
        z1 += __shfl_xor_sync(0xffffffffu, z1, off);
    }
    z0 += bp[0];
    z1 += bp[1];
    float mz = fmaxf(z0, z1);
    float e0 = __expf(z0 - mz), e1 = __expf(z1 - mz);
    float inv = 1.f / (e0 + e1);
    float a0 = e0 * inv, a1 = e1 * inv;
    float4 o;
    o.x = a0 * xo.x + a1 * xs.x;
    o.y = a0 * xo.y + a1 * xs.y;
    o.z = a0 * xo.z + a1 * xs.z;
    o.w = a0 * xo.w + a1 * xs.w;
    ((float4*)out)[v * 32 + l] = o;
}

extern "C" void kernel_launch(void* const* d_in, const int* in_sizes, int n_in,
                              void* d_out, int out_size) {
    const float* x_o    = (const float*)d_in[0];
    const float* degree = (const float*)d_in[1];
    const int *ei_o, *ei_s;
    int base;
    if (in_sizes[2] == 2 * EDGES) {
        ei_o = (const int*)d_in[2];
        ei_s = (const int*)d_in[3];
        base = 4;
    } else {
        base = 2;
        ei_o = (const int*)d_in[20];
        ei_s = (const int*)d_in[21];
    }
    const float* W_o1 = (const float*)d_in[base + 0];
    const float* a_src_o1 = (const float*)d_in[base + 1];
    const float* a_dst_o1 = (const float*)d_in[base + 2];
    const float* b_o1 = (const float*)d_in[base + 3];
    const float* W_o2 = (const float*)d_in[base + 4];
    const float* a_src_o2 = (const float*)d_in[base + 5];
    const float* a_dst_o2 = (const float*)d_in[base + 6];
    const float* b_o2 = (const float*)d_in[base + 7];
    const float* W_s1 = (const float*)d_in[base + 8];
    const float* a_src_s1 = (const float*)d_in[base + 9];
    const float* a_dst_s1 = (const float*)d_in[base + 10];
    const float* b_s1 = (const float*)d_in[base + 11];
    const float* W_s2 = (const float*)d_in[base + 12];
    const float* a_src_s2 = (const float*)d_in[base + 13];
    const float* a_dst_s2 = (const float*)d_in[base + 14];
    const float* b_s2 = (const float*)d_in[base + 15];
    const float* W_pred = (const float*)d_in[base + 16];
    const float* b_pred = (const float*)d_in[base + 17];
    float* out = (float*)d_out;

    // prep: x->fp16, deg=1 both graphs, gmax init
    k_prep<<<(NN * DD / 4 + 255) / 256, 256>>>(x_o);
    // CSR both graphs
    k_deg_count<<<(2 * EDGES + 255) / 256, 256>>>(ei_o, ei_s);
    k_scan_local<<<98, 1024>>>();
    k_scan_block<<<1, 128>>>();
    k_fill_self<<<98, 1024>>>();
    k_fill_edges<<<(2 * EDGES + 255) / 256, 256>>>(ei_o, ei_s);
    // layer 1 (both branches per launch)
    k_gemm<<<dim3((NN + 127) / 128, 2), 256>>>(0, W_o1, W_s1, a_src_o1, a_src_s1, a_dst_o1, a_dst_s1);
    k_aggregate<<<dim3(NN / 8, 2), 256>>>(0, b_o1, b_s1);
    // layer 2
    k_gemm<<<dim3((NN + 127) / 128, 2), 256>>>(1, W_o2, W_s2, a_src_o2, a_src_s2, a_dst_o2, a_dst_s2);
    k_aggregate<<<dim3(NN / 8, 2), 256>>>(1, b_o2, b_s2);
    // head
    k_pred<<<NN / 8, 256>>>(degree, W_pred, b_pred, out);
}

// round 6
// speedup vs baseline: 2.0812x; 1.1432x over previous
#include <cuda_runtime.h>
#include <cuda_fp16.h>

#define NN 50000
#define EDGES 1000000
#define DD 128
#define TOTE (EDGES + NN)

// ---------------- scratch ----------------
__device__ __half g_h16[2][NN * DD];   // per-branch transformed features
__device__ __half g_xin16[NN * DD];    // fp16 x_o
__device__ __half g_a16[2][NN * DD];   // per-branch fp16 x1
__device__ float g_ssrc[2 * NN];
__device__ float g_sdst[2 * NN];
__device__ unsigned g_gmax[8];
__device__ int   g_deg[2 * NN];
__device__ int   g_fill[2 * NN];
__device__ int   g_bsum[128];
__device__ int   g_rowptr[2 * (NN + 1)];
__device__ int   g_col[2 * TOTE];

__device__ __forceinline__ unsigned encf(float f) {
    unsigned u = __float_as_uint(f);
    return (u & 0x80000000u) ? ~u : (u | 0x80000000u);
}
__device__ __forceinline__ float decf(unsigned u) {
    return __uint_as_float((u & 0x80000000u) ? (u & 0x7fffffffu) : ~u);
}
__device__ __forceinline__ float lrelu(float z) { return z > 0.f ? z : 0.2f * z; }

// ---------------- prep: tohalf + deg/gmax init ----------------
__global__ void k_prep(const float* __restrict__ x) {
    int i = blockIdx.x * blockDim.x + threadIdx.x;
    if (i < NN * DD / 4) {
        float4 v = ((const float4*)x)[i];
        uint2 p;
        __half2 h0 = __floats2half2_rn(v.x, v.y);
        __half2 h1 = __floats2half2_rn(v.z, v.w);
        p.x = *(unsigned*)&h0;
        p.y = *(unsigned*)&h1;
        ((uint2*)g_xin16)[i] = p;
    }
    if (i < 2 * NN) g_deg[i] = 1;     // self loops, both graphs
    if (i < 8) g_gmax[i] = encf(-1e30f);
}

// ---------------- CSR build (both graphs fused) ----------------
__global__ void k_deg_count(const int* __restrict__ ei_o, const int* __restrict__ ei_s) {
    int e = blockIdx.x * blockDim.x + threadIdx.x;
    if (e < 2 * EDGES) {
        int g = (e >= EDGES);
        int le = e - g * EDGES;
        const int* ei = g ? ei_s : ei_o;
        atomicAdd(&g_deg[g * NN + ei[EDGES + le]], 1);
    }
}

__global__ void k_scan_local() {
    __shared__ int sh[1024];
    int tid = threadIdx.x;
    int g = (blockIdx.x >= 49);
    int lb = blockIdx.x - g * 49;
    int idx = lb * 1024 + tid;
    int v = (idx < NN) ? g_deg[g * NN + idx] : 0;
    sh[tid] = v;
    __syncthreads();
    for (int off = 1; off < 1024; off <<= 1) {
        int t = (tid >= off) ? sh[tid - off] : 0;
        __syncthreads();
        sh[tid] += t;
        __syncthreads();
    }
    if (idx < NN) g_rowptr[g * (NN + 1) + idx] = sh[tid] - v;
    if (tid == 1023) g_bsum[g * 64 + lb] = sh[tid];
}

// fill self loops; each block recomputes the 49-wide block-sum scan locally
__global__ void k_fill_self() {
    __shared__ int sb[64];
    int tid = threadIdx.x;
    int g = (blockIdx.x >= 49);
    int lb = blockIdx.x - g * 49;
    if (tid < 64) sb[tid] = (tid < 49) ? g_bsum[g * 64 + tid] : 0;
    __syncthreads();
    if (tid < 64) {
        // inclusive scan over 64 (single warp pair; simple serial-log in smem)
        for (int off = 1; off < 64; off <<= 1) {
            int t = (tid >= off) ? sb[tid - off] : 0;
            __syncthreads();
            sb[tid] += t;
            __syncthreads();
        }
    } else {
        for (int off = 1; off < 64; off <<= 1) { __syncthreads(); __syncthreads(); }
    }
    int boff = (lb == 0) ? 0 : sb[lb - 1];
    int idx = lb * 1024 + tid;
    if (idx < NN) {
        int p = g_rowptr[g * (NN + 1) + idx] + boff;
        g_rowptr[g * (NN + 1) + idx] = p;
        g_col[g * TOTE + p] = idx;
        g_fill[g * NN + idx] = p + 1;
    }
    if (idx == 0) g_rowptr[g * (NN + 1) + NN] = TOTE;
}

__global__ void k_fill_edges(const int* __restrict__ ei_o, const int* __restrict__ ei_s) {
    int e = blockIdx.x * blockDim.x + threadIdx.x;
    if (e < 2 * EDGES) {
        int g = (e >= EDGES);
        int le = e - g * EDGES;
        const int* ei = g ? ei_s : ei_o;
        int s = ei[le];
        int d = ei[EDGES + le];
        int pos = atomicAdd(&g_fill[g * NN + d], 1);
        g_col[g * TOTE + pos] = s;
    }
}

// ---------------- HMMA GEMM 128x128x128, both branches (grid.y) ----------------
#define APITCH 72
#define BPITCH 136

__device__ __forceinline__ void ldsm_x4(unsigned& r0, unsigned& r1, unsigned& r2, unsigned& r3,
                                        unsigned addr) {
    asm volatile("ldmatrix.sync.aligned.m8n8.x4.shared.b16 {%0,%1,%2,%3}, [%4];"
                 : "=r"(r0), "=r"(r1), "=r"(r2), "=r"(r3) : "r"(addr));
}
__device__ __forceinline__ void ldsm_x4_t(unsigned& r0, unsigned& r1, unsigned& r2, unsigned& r3,
                                          unsigned addr) {
    asm volatile("ldmatrix.sync.aligned.m8n8.x4.trans.shared.b16 {%0,%1,%2,%3}, [%4];"
                 : "=r"(r0), "=r"(r1), "=r"(r2), "=r"(r3) : "r"(addr));
}
__device__ __forceinline__ void hmma(float* d, unsigned a0, unsigned a1, unsigned a2, unsigned a3,
                                     unsigned b0, unsigned b1) {
    asm volatile("mma.sync.aligned.m16n8k16.row.col.f32.f16.f16.f32 "
                 "{%0,%1,%2,%3}, {%4,%5,%6,%7}, {%8,%9}, {%0,%1,%2,%3};"
                 : "+f"(d[0]), "+f"(d[1]), "+f"(d[2]), "+f"(d[3])
                 : "r"(a0), "r"(a1), "r"(a2), "r"(a3), "r"(b0), "r"(b1));
}

__global__ __launch_bounds__(256, 2) void k_gemm(
    int layer,
    const float* __restrict__ W0, const float* __restrict__ W1,
    const float* __restrict__ as0, const float* __restrict__ as1,
    const float* __restrict__ ad0, const float* __restrict__ ad1)
{
    int b = blockIdx.y;
    const __half* __restrict__ A = (layer == 0) ? g_xin16 : g_a16[b];
    const float* __restrict__ W = b ? W1 : W0;
    const float* __restrict__ a_src = b ? as1 : as0;
    const float* __restrict__ a_dst = b ? ad1 : ad0;
    int slot = layer * 2 + b;
    __half* __restrict__ H = g_h16[b];
    float* __restrict__ ssrc = g_ssrc + b * NN;
    float* __restrict__ sdst = g_sdst + b * NN;

    __shared__ __half Ash[128 * APITCH];
    __shared__ __half Bsh[64 * BPITCH];
    __shared__ float s_red[8][2];
    int tid = threadIdx.x;
    int l = tid & 31;
    int wid = tid >> 5;
    int row0 = blockIdx.x * 128;

    float acc[16][4];
#pragma unroll
    for (int j = 0; j < 16; ++j)
#pragma unroll
        for (int q = 0; q < 4; ++q) acc[j][q] = 0.f;

    int arow = wid * 16 + (l & 15);
    int acolo = (l >> 4) * 8;
    unsigned a_base = (unsigned)__cvta_generic_to_shared(&Ash[arow * APITCH + acolo]);
    int brow = l & 15;
    int bcolo = (l >> 4) * 8;
    unsigned b_base = (unsigned)__cvta_generic_to_shared(&Bsh[brow * BPITCH + bcolo]);

    for (int kb = 0; kb < 2; ++kb) {
#pragma unroll
        for (int t = 0; t < 4; ++t) {
            int i = tid + t * 256;
            int r = i >> 3;
            int c = i & 7;
            uint4 v = make_uint4(0u, 0u, 0u, 0u);
            if (row0 + r < NN)
                v = *(const uint4*)&A[(row0 + r) * DD + kb * 64 + c * 8];
            *(uint4*)&Ash[r * APITCH + c * 8] = v;
        }
#pragma unroll
        for (int t = 0; t < 8; ++t) {
            int i = tid + t * 256;
            int r = i >> 5;
            int c4 = i & 31;
            float4 v = *(const float4*)&W[(kb * 64 + r) * DD + c4 * 4];
            __half2 h0 = __floats2half2_rn(v.x, v.y);
            __half2 h1 = __floats2half2_rn(v.z, v.w);
            uint2 p;
            p.x = *(unsigned*)&h0;
            p.y = *(unsigned*)&h1;
            *(uint2*)&Bsh[r * BPITCH + c4 * 4] = p;
        }
        __syncthreads();
#pragma unroll
        for (int ks = 0; ks < 4; ++ks) {
            unsigned a0, a1, a2, a3;
            ldsm_x4(a0, a1, a2, a3, a_base + (unsigned)(ks * 16 * 2));
#pragma unroll
            for (int np = 0; np < 8; ++np) {
                unsigned b0, b1, b2, b3;
                ldsm_x4_t(b0, b1, b2, b3,
                          b_base + (unsigned)((ks * 16 * BPITCH + np * 16) * 2));
                hmma(acc[2 * np], a0, a1, a2, a3, b0, b1);
                hmma(acc[2 * np + 1], a0, a1, a2, a3, b2, b3);
            }
        }
        __syncthreads();
    }

    // epilogue
    int g = l >> 2, tg = l & 3;
    int r0g = row0 + wid * 16 + g;
    int r1g = r0g + 8;
    float ps0 = 0.f, pd0 = 0.f, ps1 = 0.f, pd1 = 0.f;
#pragma unroll
    for (int j = 0; j < 16; ++j) {
        int colc = j * 8 + tg * 2;
        float2 asv = *(const float2*)&a_src[colc];
        float2 adv = *(const float2*)&a_dst[colc];
        ps0 += acc[j][0] * asv.x + acc[j][1] * asv.y;
        pd0 += acc[j][0] * adv.x + acc[j][1] * adv.y;
        ps1 += acc[j][2] * asv.x + acc[j][3] * asv.y;
        pd1 += acc[j][2] * adv.x + acc[j][3] * adv.y;
        if (r0g < NN)
            *(__half2*)&H[r0g * DD + colc] = __floats2half2_rn(acc[j][0], acc[j][1]);
        if (r1g < NN)
            *(__half2*)&H[r1g * DD + colc] = __floats2half2_rn(acc[j][2], acc[j][3]);
    }
#pragma unroll
    for (int off = 1; off < 4; off <<= 1) {
        ps0 += __shfl_xor_sync(0xffffffffu, ps0, off);
        pd0 += __shfl_xor_sync(0xffffffffu, pd0, off);
        ps1 += __shfl_xor_sync(0xffffffffu, ps1, off);
        pd1 += __shfl_xor_sync(0xffffffffu, pd1, off);
    }
    float lms = -1e30f, lmd = -1e30f;
    if (tg == 0) {
        if (r0g < NN) {
            ssrc[r0g] = ps0; sdst[r0g] = pd0;
            lms = ps0; lmd = pd0;
        }
        if (r1g < NN) {
            ssrc[r1g] = ps1; sdst[r1g] = pd1;
            lms = fmaxf(lms, ps1); lmd = fmaxf(lmd, pd1);
        }
    }
#pragma unroll
    for (int off = 16; off; off >>= 1) {
        lms = fmaxf(lms, __shfl_xor_sync(0xffffffffu, lms, off));
        lmd = fmaxf(lmd, __shfl_xor_sync(0xffffffffu, lmd, off));
    }
    if (l == 0) { s_red[wid][0] = lms; s_red[wid][1] = lmd; }
    __syncthreads();
    if (tid == 0) {
        float ms = s_red[0][0], md = s_red[0][1];
#pragma unroll
        for (int i = 1; i < 8; ++i) {
            ms = fmaxf(ms, s_red[i][0]);
            md = fmaxf(md, s_red[i][1]);
        }
        atomicMax(&g_gmax[2 * slot], encf(ms));
        atomicMax(&g_gmax[2 * slot + 1], encf(md));
    }
}

// ---------------- shared edge-softmax accumulate (warp-per-dst) ----------------
__device__ __forceinline__ void agg_row(const int* __restrict__ col,
                                        const float* __restrict__ ss,
                                        const uint2* __restrict__ h2,
                                        int beg, int end, int l,
                                        float sd, float c,
                                        float4& acc, float& den) {
    int e = beg;
    for (; e + 8 <= end; e += 8) {
        int s[8];
        float wt[8];
#pragma unroll
        for (int q = 0; q < 8; ++q) s[q] = col[e + q];
#pragma unroll
        for (int q = 0; q < 8; ++q) wt[q] = __expf(lrelu(ss[s[q]] + sd) - c);
#pragma unroll
        for (int q = 0; q < 8; ++q) {
            uint2 r = h2[s[q] * 32 + l];
            float2 a = __half22float2(*(__half2*)&r.x);
            float2 b = __half22float2(*(__half2*)&r.y);
            den += wt[q];
            acc.x += wt[q] * a.x; acc.y += wt[q] * a.y;
            acc.z += wt[q] * b.x; acc.w += wt[q] * b.y;
        }
    }
    for (; e < end; ++e) {
        int s = col[e];
        float wgt = __expf(lrelu(ss[s] + sd) - c);
        uint2 r = h2[s * 32 + l];
        float2 a = __half22float2(*(__half2*)&r.x);
        float2 b = __half22float2(*(__half2*)&r.y);
        den += wgt;
        acc.x += wgt * a.x; acc.y += wgt * a.y;
        acc.z += wgt * b.x; acc.w += wgt * b.y;
    }
}

// ---------------- layer-1 aggregate (both branches via grid.y) ----------------
__global__ __launch_bounds__(256) void k_aggregate1(const float* __restrict__ bias0,
                                                    const float* __restrict__ bias1) {
    int b = blockIdx.y;
    const int* __restrict__ rowptr = g_rowptr + b * (NN + 1);
    const int* __restrict__ col    = g_col + b * TOTE;
    const float* __restrict__ bias = b ? bias1 : bias0;
    int w = (blockIdx.x * blockDim.x + threadIdx.x) >> 5;
    int l = threadIdx.x & 31;
    if (w >= NN) return;
    float c = lrelu(decf(g_gmax[2 * b]) + decf(g_gmax[2 * b + 1]));
    float sd = g_sdst[b * NN + w];
    float4 acc = make_float4(0.f, 0.f, 0.f, 0.f);
    float den = 0.f;
    agg_row(col, g_ssrc + b * NN, (const uint2*)g_h16[b],
            rowptr[w], rowptr[w + 1], l, sd, c, acc, den);
    float inv = 1.f / (den + 1e-16f);
    float2 bv0 = ((const float2*)bias)[2 * l];
    float2 bv1 = ((const float2*)bias)[2 * l + 1];
    float4 o;
    o.x = fmaxf(acc.x * inv + bv0.x, 0.f);
    o.y = fmaxf(acc.y * inv + bv0.y, 0.f);
    o.z = fmaxf(acc.z * inv + bv1.x, 0.f);
    o.w = fmaxf(acc.w * inv + bv1.y, 0.f);
    __half2 h0 = __floats2half2_rn(o.x, o.y);
    __half2 h1 = __floats2half2_rn(o.z, o.w);
    uint2 p;
    p.x = *(unsigned*)&h0;
    p.y = *(unsigned*)&h1;
    ((uint2*)g_a16[b])[w * 32 + l] = p;
}

// ---------------- layer-2 aggregate (both branches per warp) + fused pred head ----------------
__global__ __launch_bounds__(256) void k_agg2pred(const float* __restrict__ bias0,
                                                  const float* __restrict__ bias1,
                                                  const float* __restrict__ degree,
                                                  const float* __restrict__ Wp,
                                                  const float* __restrict__ bp,
                                                  float* __restrict__ out) {
    int w = (blockIdx.x * blockDim.x + threadIdx.x) >> 5;
    int l = threadIdx.x & 31;
    if (w >= NN) return;
    float4 xb[2];
#pragma unroll
    for (int b = 0; b < 2; ++b) {
        const int* __restrict__ rowptr = g_rowptr + b * (NN + 1);
        const int* __restrict__ col    = g_col + b * TOTE;
        const float* __restrict__ bias = b ? bias1 : bias0;
        float c = lrelu(decf(g_gmax[4 + 2 * b]) + decf(g_gmax[4 + 2 * b + 1]));
        float sd = g_sdst[b * NN + w];
        float4 acc = make_float4(0.f, 0.f, 0.f, 0.f);
        float den = 0.f;
        agg_row(col, g_ssrc + b * NN, (const uint2*)g_h16[b],
                rowptr[w], rowptr[w + 1], l, sd, c, acc, den);
        float inv = 1.f / (den + 1e-16f);
        float2 bv0 = ((const float2*)bias)[2 * l];
        float2 bv1 = ((const float2*)bias)[2 * l + 1];
        xb[b].x = acc.x * inv + bv0.x;
        xb[b].y = acc.y * inv + bv0.y;
        xb[b].z = acc.z * inv + bv1.x;
        xb[b].w = acc.w * inv + bv1.y;
    }
    // prediction head (lane l owns dims 4l..4l+3)
    float4 xo = xb[0], xs = xb[1];
    float dg = degree[w * 32 + l];
    int k0 = l * 4;
    float z0 = xo.x * Wp[(k0 + 0) * 2] + xo.y * Wp[(k0 + 1) * 2]
             + xo.z * Wp[(k0 + 2) * 2] + xo.w * Wp[(k0 + 3) * 2]
             + xs.x * Wp[(128 + k0 + 0) * 2] + xs.y * Wp[(128 + k0 + 1) * 2]
             + xs.z * Wp[(128 + k0 + 2) * 2] + xs.w * Wp[(128 + k0 + 3) * 2]
             + dg * Wp[(256 + l) * 2];
    float z1 = xo.x * Wp[(k0 + 0) * 2 + 1] + xo.y * Wp[(k0 + 1) * 2 + 1]
             + xo.z * Wp[(k0 + 2) * 2 + 1] + xo.w * Wp[(k0 + 3) * 2 + 1]
             + xs.x * Wp[(128 + k0 + 0) * 2 + 1] + xs.y * Wp[(128 + k0 + 1) * 2 + 1]
             + xs.z * Wp[(128 + k0 + 2) * 2 + 1] + xs.w * Wp[(128 + k0 + 3) * 2 + 1]
             + dg * Wp[(256 + l) * 2 + 1];
#pragma unroll
    for (int off = 16; off; off >>= 1) {
        z0 += __shfl_xor_sync(0xffffffffu, z0, off);
        z1 += __shfl_xor_sync(0xffffffffu, z1, off);
    }
    z0 += bp[0];
    z1 += bp[1];
    float mz = fmaxf(z0, z1);
    float e0 = __expf(z0 - mz), e1 = __expf(z1 - mz);
    float inv = 1.f / (e0 + e1);
    float a0 = e0 * inv, a1 = e1 * inv;
    float4 o;
    o.x = a0 * xo.x + a1 * xs.x;
    o.y = a0 * xo.y + a1 * xs.y;
    o.z = a0 * xo.z + a1 * xs.z;
    o.w = a0 * xo.w + a1 * xs.w;
    ((float4*)out)[w * 32 + l] = o;
}

extern "C" void kernel_launch(void* const* d_in, const int* in_sizes, int n_in,
                              void* d_out, int out_size) {
    const float* x_o    = (const float*)d_in[0];
    const float* degree = (const float*)d_in[1];
    const int *ei_o, *ei_s;
    int base;
    if (in_sizes[2] == 2 * EDGES) {
        ei_o = (const int*)d_in[2];
        ei_s = (const int*)d_in[3];
        base = 4;
    } else {
        base = 2;
        ei_o = (const int*)d_in[20];
        ei_s = (const int*)d_in[21];
    }
    const float* W_o1 = (const float*)d_in[base + 0];
    const float* a_src_o1 = (const float*)d_in[base + 1];
    const float* a_dst_o1 = (const float*)d_in[base + 2];
    const float* b_o1 = (const float*)d_in[base + 3];
    const float* W_o2 = (const float*)d_in[base + 4];
    const float* a_src_o2 = (const float*)d_in[base + 5];
    const float* a_dst_o2 = (const float*)d_in[base + 6];
    const float* b_o2 = (const float*)d_in[base + 7];
    const float* W_s1 = (const float*)d_in[base + 8];
    const float* a_src_s1 = (const float*)d_in[base + 9];
    const float* a_dst_s1 = (const float*)d_in[base + 10];
    const float* b_s1 = (const float*)d_in[base + 11];
    const float* W_s2 = (const float*)d_in[base + 12];
    const float* a_src_s2 = (const float*)d_in[base + 13];
    const float* a_dst_s2 = (const float*)d_in[base + 14];
    const float* b_s2 = (const float*)d_in[base + 15];
    const float* W_pred = (const float*)d_in[base + 16];
    const float* b_pred = (const float*)d_in[base + 17];
    float* out = (float*)d_out;

    k_prep<<<(NN * DD / 4 + 255) / 256, 256>>>(x_o);
    k_deg_count<<<(2 * EDGES + 255) / 256, 256>>>(ei_o, ei_s);
    k_scan_local<<<98, 1024>>>();
    k_fill_self<<<98, 1024>>>();
    k_fill_edges<<<(2 * EDGES + 255) / 256, 256>>>(ei_o, ei_s);
    k_gemm<<<dim3((NN + 127) / 128, 2), 256>>>(0, W_o1, W_s1, a_src_o1, a_src_s1, a_dst_o1, a_dst_s1);
    k_aggregate1<<<dim3(NN / 8, 2), 256>>>(b_o1, b_s1);
    k_gemm<<<dim3((NN + 127) / 128, 2), 256>>>(1, W_o2, W_s2, a_src_o2, a_src_s2, a_dst_o2, a_dst_s2);
    k_agg2pred<<<NN / 8, 256>>>(b_o2, b_s2, degree, W_pred, b_pred, out);
}

// round 7
// speedup vs baseline: 2.1124x; 1.0150x over previous
#include <cuda_runtime.h>
#include <cuda_fp16.h>

#define NN 50000
#define EDGES 1000000
#define DD 128
#define TOTE (EDGES + NN)

// ---------------- scratch ----------------
__device__ __half g_h16[2][NN * DD];   // per-branch transformed features
__device__ __half g_xin16[NN * DD];    // fp16 x_o
__device__ __half g_a16[2][NN * DD];   // per-branch fp16 x1
__device__ float g_ssrc[2 * NN];
__device__ float g_sdst[2 * NN];
__device__ unsigned g_gmax[8];
__device__ int   g_deg[2 * NN];        // zeroed at end of each run (fill_self)
__device__ int   g_fill[2 * NN];
__device__ int   g_bsum[128];
__device__ int   g_rowptr[2 * (NN + 1)];
__device__ int   g_col[2 * TOTE];

__device__ __forceinline__ unsigned encf(float f) {
    unsigned u = __float_as_uint(f);
    return (u & 0x80000000u) ? ~u : (u | 0x80000000u);
}
__device__ __forceinline__ float decf(unsigned u) {
    return __uint_as_float((u & 0x80000000u) ? (u & 0x7fffffffu) : ~u);
}
__device__ __forceinline__ float lrelu(float z) { return z > 0.f ? z : 0.2f * z; }

// ---------------- merged: tohalf/gmax-init + degree count ----------------
#define PREP_BLKS 6250   // NN*DD/4 / 256
__global__ void k_prep_count(const float* __restrict__ x,
                             const int* __restrict__ ei_o,
                             const int* __restrict__ ei_s) {
    if (blockIdx.x < PREP_BLKS) {
        int i = blockIdx.x * 256 + threadIdx.x;
        if (i < NN * DD / 4) {
            float4 v = ((const float4*)x)[i];
            uint2 p;
            __half2 h0 = __floats2half2_rn(v.x, v.y);
            __half2 h1 = __floats2half2_rn(v.z, v.w);
            p.x = *(unsigned*)&h0;
            p.y = *(unsigned*)&h1;
            ((uint2*)g_xin16)[i] = p;
        }
        if (i < 8) g_gmax[i] = encf(-1e30f);
    } else {
        int e = (blockIdx.x - PREP_BLKS) * 256 + threadIdx.x;
        if (e < 2 * EDGES) {
            int g = (e >= EDGES);
            int le = e - g * EDGES;
            const int* ei = g ? ei_s : ei_o;
            atomicAdd(&g_deg[g * NN + ei[EDGES + le]], 1);
        }
    }
}

// ---------------- local scan (shuffle-based); +1 self loop folded in ----------------
__global__ void k_scan_local() {
    __shared__ int wsum[32];
    int tid = threadIdx.x;
    int lane = tid & 31;
    int wid = tid >> 5;
    int g = (blockIdx.x >= 49);
    int lb = blockIdx.x - g * 49;
    int idx = lb * 1024 + tid;
    int v = (idx < NN) ? (g_deg[g * NN + idx] + 1) : 0;   // +1 = self loop
    int sc = v;
#pragma unroll
    for (int off = 1; off < 32; off <<= 1) {
        int t = __shfl_up_sync(0xffffffffu, sc, off);
        if (lane >= off) sc += t;
    }
    if (lane == 31) wsum[wid] = sc;
    __syncthreads();
    if (wid == 0) {
        int wv = wsum[lane];
        int ws = wv;
#pragma unroll
        for (int off = 1; off < 32; off <<= 1) {
            int t = __shfl_up_sync(0xffffffffu, ws, off);
            if (lane >= off) ws += t;
        }
        wsum[lane] = ws;
    }
    __syncthreads();
    int incl = sc + (wid ? wsum[wid - 1] : 0);
    if (idx < NN) g_rowptr[g * (NN + 1) + idx] = incl - v;
    if (tid == 1023) g_bsum[g * 64 + lb] = incl;
}

// fill self loops; each block recomputes the 49-wide block-sum scan locally;
// also re-zeros g_deg for the next graph replay
__global__ void k_fill_self() {
    __shared__ int sb[64];
    int tid = threadIdx.x;
    int g = (blockIdx.x >= 49);
    int lb = blockIdx.x - g * 49;
    if (tid < 64) sb[tid] = (tid < 49) ? g_bsum[g * 64 + tid] : 0;
    __syncthreads();
    if (tid < 64) {
        for (int off = 1; off < 64; off <<= 1) {
            int t = (tid >= off) ? sb[tid - off] : 0;
            __syncthreads();
            sb[tid] += t;
            __syncthreads();
        }
    } else {
        for (int off = 1; off < 64; off <<= 1) { __syncthreads(); __syncthreads(); }
    }
    int boff = (lb == 0) ? 0 : sb[lb - 1];
    int idx = lb * 1024 + tid;
    if (idx < NN) {
        int p = g_rowptr[g * (NN + 1) + idx] + boff;
        g_rowptr[g * (NN + 1) + idx] = p;
        g_col[g * TOTE + p] = idx;
        g_fill[g * NN + idx] = p + 1;
        g_deg[g * NN + idx] = 0;      // reset for next run
    }
    if (idx == 0) g_rowptr[g * (NN + 1) + NN] = TOTE;
}

// ---------------- HMMA GEMM tile body (shared by both layers) ----------------
#define APITCH 72
#define BPITCH 136

__device__ __forceinline__ void ldsm_x4(unsigned& r0, unsigned& r1, unsigned& r2, unsigned& r3,
                                        unsigned addr) {
    asm volatile("ldmatrix.sync.aligned.m8n8.x4.shared.b16 {%0,%1,%2,%3}, [%4];"
                 : "=r"(r0), "=r"(r1), "=r"(r2), "=r"(r3) : "r"(addr));
}
__device__ __forceinline__ void ldsm_x4_t(unsigned& r0, unsigned& r1, unsigned& r2, unsigned& r3,
                                          unsigned addr) {
    asm volatile("ldmatrix.sync.aligned.m8n8.x4.trans.shared.b16 {%0,%1,%2,%3}, [%4];"
                 : "=r"(r0), "=r"(r1), "=r"(r2), "=r"(r3) : "r"(addr));
}
__device__ __forceinline__ void hmma(float* d, unsigned a0, unsigned a1, unsigned a2, unsigned a3,
                                     unsigned b0, unsigned b1) {
    asm volatile("mma.sync.aligned.m16n8k16.row.col.f32.f16.f16.f32 "
                 "{%0,%1,%2,%3}, {%4,%5,%6,%7}, {%8,%9}, {%0,%1,%2,%3};"
                 : "+f"(d[0]), "+f"(d[1]), "+f"(d[2]), "+f"(d[3])
                 : "r"(a0), "r"(a1), "r"(a2), "r"(a3), "r"(b0), "r"(b1));
}

__device__ void gemm_tile(int layer, int b, int tile,
                          const float* __restrict__ W,
                          const float* __restrict__ a_src,
                          const float* __restrict__ a_dst) {
    const __half* __restrict__ A = (layer == 0) ? g_xin16 : g_a16[b];
    int slot = layer * 2 + b;
    __half* __restrict__ H = g_h16[b];
    float* __restrict__ ssrc = g_ssrc + b * NN;
    float* __restrict__ sdst = g_sdst + b * NN;

    __shared__ __half Ash[128 * APITCH];
    __shared__ __half Bsh[64 * BPITCH];
    __shared__ float s_red[8][2];
    int tid = threadIdx.x;
    int l = tid & 31;
    int wid = tid >> 5;
    int row0 = tile * 128;

    float acc[16][4];
#pragma unroll
    for (int j = 0; j < 16; ++j)
#pragma unroll
        for (int q = 0; q < 4; ++q) acc[j][q] = 0.f;

    int arow = wid * 16 + (l & 15);
    int acolo = (l >> 4) * 8;
    unsigned a_base = (unsigned)__cvta_generic_to_shared(&Ash[arow * APITCH + acolo]);
    int brow = l & 15;
    int bcolo = (l >> 4) * 8;
    unsigned b_base = (unsigned)__cvta_generic_to_shared(&Bsh[brow * BPITCH + bcolo]);

    for (int kb = 0; kb < 2; ++kb) {
#pragma unroll
        for (int t = 0; t < 4; ++t) {
            int i = tid + t * 256;
            int r = i >> 3;
            int c = i & 7;
            uint4 v = make_uint4(0u, 0u, 0u, 0u);
            if (row0 + r < NN)
                v = *(const uint4*)&A[(row0 + r) * DD + kb * 64 + c * 8];
            *(uint4*)&Ash[r * APITCH + c * 8] = v;
        }
#pragma unroll
        for (int t = 0; t < 8; ++t) {
            int i = tid + t * 256;
            int r = i >> 5;
            int c4 = i & 31;
            float4 v = *(const float4*)&W[(kb * 64 + r) * DD + c4 * 4];
            __half2 h0 = __floats2half2_rn(v.x, v.y);
            __half2 h1 = __floats2half2_rn(v.z, v.w);
            uint2 p;
            p.x = *(unsigned*)&h0;
            p.y = *(unsigned*)&h1;
            *(uint2*)&Bsh[r * BPITCH + c4 * 4] = p;
        }
        __syncthreads();
#pragma unroll
        for (int ks = 0; ks < 4; ++ks) {
            unsigned a0, a1, a2, a3;
            ldsm_x4(a0, a1, a2, a3, a_base + (unsigned)(ks * 16 * 2));
#pragma unroll
            for (int np = 0; np < 8; ++np) {
                unsigned b0, b1, b2, b3;
                ldsm_x4_t(b0, b1, b2, b3,
                          b_base + (unsigned)((ks * 16 * BPITCH + np * 16) * 2));
                hmma(acc[2 * np], a0, a1, a2, a3, b0, b1);
                hmma(acc[2 * np + 1], a0, a1, a2, a3, b2, b3);
            }
        }
        __syncthreads();
    }

    int g = l >> 2, tg = l & 3;
    int r0g = row0 + wid * 16 + g;
    int r1g = r0g + 8;
    float ps0 = 0.f, pd0 = 0.f, ps1 = 0.f, pd1 = 0.f;
#pragma unroll
    for (int j = 0; j < 16; ++j) {
        int colc = j * 8 + tg * 2;
        float2 asv = *(const float2*)&a_src[colc];
        float2 adv = *(const float2*)&a_dst[colc];
        ps0 += acc[j][0] * asv.x + acc[j][1] * asv.y;
        pd0 += acc[j][0] * adv.x + acc[j][1] * adv.y;
        ps1 += acc[j][2] * asv.x + acc[j][3] * asv.y;
        pd1 += acc[j][2] * adv.x + acc[j][3] * adv.y;
        if (r0g < NN)
            *(__half2*)&H[r0g * DD + colc] = __floats2half2_rn(acc[j][0], acc[j][1]);
        if (r1g < NN)
            *(__half2*)&H[r1g * DD + colc] = __floats2half2_rn(acc[j][2], acc[j][3]);
    }
#pragma unroll
    for (int off = 1; off < 4; off <<= 1) {
        ps0 += __shfl_xor_sync(0xffffffffu, ps0, off);
        pd0 += __shfl_xor_sync(0xffffffffu, pd0, off);
        ps1 += __shfl_xor_sync(0xffffffffu, ps1, off);
        pd1 += __shfl_xor_sync(0xffffffffu, pd1, off);
    }
    float lms = -1e30f, lmd = -1e30f;
    if (tg == 0) {
        if (r0g < NN) {
            ssrc[r0g] = ps0; sdst[r0g] = pd0;
            lms = ps0; lmd = pd0;
        }
        if (r1g < NN) {
            ssrc[r1g] = ps1; sdst[r1g] = pd1;
            lms = fmaxf(lms, ps1); lmd = fmaxf(lmd, pd1);
        }
    }
#pragma unroll
    for (int off = 16; off; off >>= 1) {
        lms = fmaxf(lms, __shfl_xor_sync(0xffffffffu, lms, off));
        lmd = fmaxf(lmd, __shfl_xor_sync(0xffffffffu, lmd, off));
    }
    if (l == 0) { s_red[wid][0] = lms; s_red[wid][1] = lmd; }
    __syncthreads();
    if (tid == 0) {
        float ms = s_red[0][0], md = s_red[0][1];
#pragma unroll
        for (int i = 1; i < 8; ++i) {
            ms = fmaxf(ms, s_red[i][0]);
            md = fmaxf(md, s_red[i][1]);
        }
        atomicMax(&g_gmax[2 * slot], encf(ms));
        atomicMax(&g_gmax[2 * slot + 1], encf(md));
    }
}

// ---------------- merged: layer-1 GEMM (both branches) + edge fill ----------------
#define GEMM_TILES 392          // ceil(NN/128)
#define GEMM_BLKS (2 * GEMM_TILES)
__global__ __launch_bounds__(256, 2) void k_gemm1_fill(
    const float* __restrict__ W0, const float* __restrict__ W1,
    const float* __restrict__ as0, const float* __restrict__ as1,
    const float* __restrict__ ad0, const float* __restrict__ ad1,
    const int* __restrict__ ei_o, const int* __restrict__ ei_s)
{
    if (blockIdx.x < GEMM_BLKS) {
        int b = (blockIdx.x >= GEMM_TILES);
        int tile = blockIdx.x - b * GEMM_TILES;
        gemm_tile(0, b, tile, b ? W1 : W0, b ? as1 : as0, b ? ad1 : ad0);
    } else {
        int e = (blockIdx.x - GEMM_BLKS) * 256 + threadIdx.x;
        if (e < 2 * EDGES) {
            int g = (e >= EDGES);
            int le = e - g * EDGES;
            const int* ei = g ? ei_s : ei_o;
            int s = ei[le];
            int d = ei[EDGES + le];
            int pos = atomicAdd(&g_fill[g * NN + d], 1);
            g_col[g * TOTE + pos] = s;
        }
    }
}

// ---------------- layer-2 GEMM (both branches) ----------------
__global__ __launch_bounds__(256, 2) void k_gemm2(
    const float* __restrict__ W0, const float* __restrict__ W1,
    const float* __restrict__ as0, const float* __restrict__ as1,
    const float* __restrict__ ad0, const float* __restrict__ ad1)
{
    int b = blockIdx.y;
    gemm_tile(1, b, blockIdx.x, b ? W1 : W0, b ? as1 : as0, b ? ad1 : ad0);
}

// ---------------- shared edge-softmax accumulate (warp-per-dst) ----------------
__device__ __forceinline__ void agg_row(const int* __restrict__ col,
                                        const float* __restrict__ ss,
                                        const uint2* __restrict__ h2,
                                        int beg, int end, int l,
                                        float sd, float c,
                                        float4& acc, float& den) {
    int e = beg;
    for (; e + 8 <= end; e += 8) {
        int s[8];
        float wt[8];
#pragma unroll
        for (int q = 0; q < 8; ++q) s[q] = col[e + q];
#pragma unroll
        for (int q = 0; q < 8; ++q) wt[q] = __expf(lrelu(ss[s[q]] + sd) - c);
#pragma unroll
        for (int q = 0; q < 8; ++q) {
            uint2 r = h2[s[q] * 32 + l];
            float2 a = __half22float2(*(__half2*)&r.x);
            float2 b = __half22float2(*(__half2*)&r.y);
            den += wt[q];
            acc.x += wt[q] * a.x; acc.y += wt[q] * a.y;
            acc.z += wt[q] * b.x; acc.w += wt[q] * b.y;
        }
    }
    for (; e < end; ++e) {
        int s = col[e];
        float wgt = __expf(lrelu(ss[s] + sd) - c);
        uint2 r = h2[s * 32 + l];
        float2 a = __half22float2(*(__half2*)&r.x);
        float2 b = __half22float2(*(__half2*)&r.y);
        den += wgt;
        acc.x += wgt * a.x; acc.y += wgt * a.y;
        acc.z += wgt * b.x; acc.w += wgt * b.y;
    }
}

// ---------------- layer-1 aggregate (both branches via grid.y) ----------------
__global__ __launch_bounds__(256) void k_aggregate1(const float* __restrict__ bias0,
                                                    const float* __restrict__ bias1) {
    int b = blockIdx.y;
    const int* __restrict__ rowptr = g_rowptr + b * (NN + 1);
    const int* __restrict__ col    = g_col + b * TOTE;
    const float* __restrict__ bias = b ? bias1 : bias0;
    int w = (blockIdx.x * blockDim.x + threadIdx.x) >> 5;
    int l = threadIdx.x & 31;
    if (w >= NN) return;
    float c = lrelu(decf(g_gmax[2 * b]) + decf(g_gmax[2 * b + 1]));
    float sd = g_sdst[b * NN + w];
    float4 acc = make_float4(0.f, 0.f, 0.f, 0.f);
    float den = 0.f;
    agg_row(col, g_ssrc + b * NN, (const uint2*)g_h16[b],
            rowptr[w], rowptr[w + 1], l, sd, c, acc, den);
    float inv = 1.f / (den + 1e-16f);
    float2 bv0 = ((const float2*)bias)[2 * l];
    float2 bv1 = ((const float2*)bias)[2 * l + 1];
    float4 o;
    o.x = fmaxf(acc.x * inv + bv0.x, 0.f);
    o.y = fmaxf(acc.y * inv + bv0.y, 0.f);
    o.z = fmaxf(acc.z * inv + bv1.x, 0.f);
    o.w = fmaxf(acc.w * inv + bv1.y, 0.f);
    __half2 h0 = __floats2half2_rn(o.x, o.y);
    __half2 h1 = __floats2half2_rn(o.z, o.w);
    uint2 p;
    p.x = *(unsigned*)&h0;
    p.y = *(unsigned*)&h1;
    ((uint2*)g_a16[b])[w * 32 + l] = p;
}

// ---------------- layer-2 aggregate (both branches per warp) + fused pred head ----------------
__global__ __launch_bounds__(256) void k_agg2pred(const float* __restrict__ bias0,
                                                  const float* __restrict__ bias1,
                                                  const float* __restrict__ degree,
                                                  const float* __restrict__ Wp,
                                                  const float* __restrict__ bp,
                                                  float* __restrict__ out) {
    int w = (blockIdx.x * blockDim.x + threadIdx.x) >> 5;
    int l = threadIdx.x & 31;
    if (w >= NN) return;
    float4 xb[2];
#pragma unroll
    for (int b = 0; b < 2; ++b) {
        const int* __restrict__ rowptr = g_rowptr + b * (NN + 1);
        const int* __restrict__ col    = g_col + b * TOTE;
        const float* __restrict__ bias = b ? bias1 : bias0;
        float c = lrelu(decf(g_gmax[4 + 2 * b]) + decf(g_gmax[4 + 2 * b + 1]));
        float sd = g_sdst[b * NN + w];
        float4 acc = make_float4(0.f, 0.f, 0.f, 0.f);
        float den = 0.f;
        agg_row(col, g_ssrc + b * NN, (const uint2*)g_h16[b],
                rowptr[w], rowptr[w + 1], l, sd, c, acc, den);
        float inv = 1.f / (den + 1e-16f);
        float2 bv0 = ((const float2*)bias)[2 * l];
        float2 bv1 = ((const float2*)bias)[2 * l + 1];
        xb[b].x = acc.x * inv + bv0.x;
        xb[b].y = acc.y * inv + bv0.y;
        xb[b].z = acc.z * inv + bv1.x;
        xb[b].w = acc.w * inv + bv1.y;
    }
    float4 xo = xb[0], xs = xb[1];
    float dg = degree[w * 32 + l];
    int k0 = l * 4;
    float z0 = xo.x * Wp[(k0 + 0) * 2] + xo.y * Wp[(k0 + 1) * 2]
             + xo.z * Wp[(k0 + 2) * 2] + xo.w * Wp[(k0 + 3) * 2]
             + xs.x * Wp[(128 + k0 + 0) * 2] + xs.y * Wp[(128 + k0 + 1) * 2]
             + xs.z * Wp[(128 + k0 + 2) * 2] + xs.w * Wp[(128 + k0 + 3) * 2]
             + dg * Wp[(256 + l) * 2];
    float z1 = xo.x * Wp[(k0 + 0) * 2 + 1] + xo.y * Wp[(k0 + 1) * 2 + 1]
             + xo.z * Wp[(k0 + 2) * 2 + 1] + xo.w * Wp[(k0 + 3) * 2 + 1]
             + xs.x * Wp[(128 + k0 + 0) * 2 + 1] + xs.y * Wp[(128 + k0 + 1) * 2 + 1]
             + xs.z * Wp[(128 + k0 + 2) * 2 + 1] + xs.w * Wp[(128 + k0 + 3) * 2 + 1]
             + dg * Wp[(256 + l) * 2 + 1];
#pragma unroll
    for (int off = 16; off; off >>= 1) {
        z0 += __shfl_xor_sync(0xffffffffu, z0, off);
        z1 += __shfl_xor_sync(0xffffffffu, z1, off);
    }
    z0 += bp[0];
    z1 += bp[1];
    float mz = fmaxf(z0, z1);
    float e0 = __expf(z0 - mz), e1 = __expf(z1 - mz);
    float inv = 1.f / (e0 + e1);
    float a0 = e0 * inv, a1 = e1 * inv;
    float4 o;
    o.x = a0 * xo.x + a1 * xs.x;
    o.y = a0 * xo.y + a1 * xs.y;
    o.z = a0 * xo.z + a1 * xs.z;
    o.w = a0 * xo.w + a1 * xs.w;
    ((float4*)out)[w * 32 + l] = o;
}

extern "C" void kernel_launch(void* const* d_in, const int* in_sizes, int n_in,
                              void* d_out, int out_size) {
    const float* x_o    = (const float*)d_in[0];
    const float* degree = (const float*)d_in[1];
    const int *ei_o, *ei_s;
    int base;
    if (in_sizes[2] == 2 * EDGES) {
        ei_o = (const int*)d_in[2];
        ei_s = (const int*)d_in[3];
        base = 4;
    } else {
        base = 2;
        ei_o = (const int*)d_in[20];
        ei_s = (const int*)d_in[21];
    }
    const float* W_o1 = (const float*)d_in[base + 0];
    const float* a_src_o1 = (const float*)d_in[base + 1];
    const float* a_dst_o1 = (const float*)d_in[base + 2];
    const float* b_o1 = (const float*)d_in[base + 3];
    const float* W_o2 = (const float*)d_in[base + 4];
    const float* a_src_o2 = (const float*)d_in[base + 5];
    const float* a_dst_o2 = (const float*)d_in[base + 6];
    const float* b_o2 = (const float*)d_in[base + 7];
    const float* W_s1 = (const float*)d_in[base + 8];
    const float* a_src_s1 = (const float*)d_in[base + 9];
    const float* a_dst_s1 = (const float*)d_in[base + 10];
    const float* b_s1 = (const float*)d_in[base + 11];
    const float* W_s2 = (const float*)d_in[base + 12];
    const float* a_src_s2 = (const float*)d_in[base + 13];
    const float* a_dst_s2 = (const float*)d_in[base + 14];
    const float* b_s2 = (const float*)d_in[base + 15];
    const float* W_pred = (const float*)d_in[base + 16];
    const float* b_pred = (const float*)d_in[base + 17];
    float* out = (float*)d_out;

    int count_blks = (2 * EDGES + 255) / 256;
    k_prep_count<<<PREP_BLKS + count_blks, 256>>>(x_o, ei_o, ei_s);
    k_scan_local<<<98, 1024>>>();
    k_fill_self<<<98, 1024>>>();
    k_gemm1_fill<<<GEMM_BLKS + count_blks, 256>>>(W_o1, W_s1, a_src_o1, a_src_s1,
                                                  a_dst_o1, a_dst_s1, ei_o, ei_s);
    k_aggregate1<<<dim3(NN / 8, 2), 256>>>(b_o1, b_s1);
    k_gemm2<<<dim3(GEMM_TILES, 2), 256>>>(W_o2, W_s2, a_src_o2, a_src_s2, a_dst_o2, a_dst_s2);
    k_agg2pred<<<NN / 8, 256>>>(b_o2, b_s2, degree, W_pred, b_pred, out);
}